// round 9
// baseline (speedup 1.0000x reference)
#include <cuda_runtime.h>
#include <math.h>
#include <stdint.h>

// Problem constants
#define BV 512
#define TV 64
#define FV 256
#define HV 1024

// Output layout: x_imp [B,T,F] | reconstruction [B,T,F] | h_fin [B,H] | x_loss | kl_loss
#define OFF_REC   (BV*TV*FV)
#define OFF_HFIN  (2*BV*TV*FV)
#define OFF_LOSS  (2*BV*TV*FV + BV*HV)

#define NB2 32    // loss partial tiles per step
#define PGRID 208 // persistent kernel grid (<= 2 blocks/SM on 148 SMs)

// ---------------- scratch ----------------
__device__ float g_h[BV*HV];
__device__ float g_xh[BV*FV];
__device__ float g_gh[BV*3*HV];
__device__ float g_gi[BV*3*HV];
__device__ float g_gammaH[(size_t)TV*BV*HV];
__device__ float g_beta[(size_t)TV*BV*FV];
__device__ float g_msum[TV];
__device__ float g_lossPart[TV*NB2];

// grid-wide barrier state
__device__ unsigned g_barCnt = 0;
__device__ unsigned g_barGen = 0;

// ---- pre-swizzled tf32 B (weights), uint2 fragment granularity ----
#define SZ2(N,K) ((N)*(K)/2)
#define BOFF_G1 0
#define BOFF_G3 (BOFF_G1 + SZ2(3328,1024))
#define BOFF_G2 (BOFF_G3 + SZ2(3072,512))
#define BOFF_P1 (BOFF_G2 + SZ2(256,256))
#define BOFF_P2 (BOFF_P1 + SZ2(1024,256))
#define BSWZ_TOTAL (BOFF_P2 + SZ2(256,512))
__device__ uint2 g_Bswz[BSWZ_TOTAL];

// ---- pre-swizzled tf32 A (activations), uint32 words, 16B-aligned ----
#define AOFF_G1 0                                   // 512x1024
#define AOFF_G2 (AOFF_G1 + BV*HV)                   // 512x256
#define AOFF_G3 (AOFF_G2 + BV*FV)                   // 64 slices of 512x512
#define AG3_STRIDE (BV*2*FV)
#define AOFF_P1 (AOFF_G3 + TV*AG3_STRIDE)           // 32768x256
#define AOFF_P2 (AOFF_P1 + TV*BV*FV)                // 32768x512
#define ASWZ_TOTAL (AOFF_P2 + TV*BV*2*FV)
__device__ uint4 g_Aswz4[ASWZ_TOTAL/4];
#define ASWZ_W ((uint32_t*)g_Aswz4)

__device__ __forceinline__ uint32_t f2tf(float f) {
    uint32_t r;
    asm("cvt.rna.tf32.f32 %0, %1;" : "=r"(r) : "f"(f));
    return r;
}

// word index of element (m,k) in fragment-native A layout (KTT = K/8)
__device__ __forceinline__ int aidx(int m, int k, int KTT) {
    int r = m & 15, c = k & 7;
    return (((m >> 4)*KTT + (k >> 3))*32 + (r & 7)*4 + (c & 3))*4
           + (r >> 3) + (((k >> 2) & 1) << 1);
}

// ---------------- grid-wide barrier ----------------
__device__ __forceinline__ void gridsync() {
    __threadfence();            // release prior writes device-wide
    __syncthreads();
    if (threadIdx.x == 0) {
        unsigned gen = *(volatile unsigned*)&g_barGen;
        if (atomicAdd(&g_barCnt, 1u) == (unsigned)gridDim.x - 1u) {
            g_barCnt = 0;
            __threadfence();
            atomicExch(&g_barGen, gen + 1u);
        } else {
            while (*(volatile unsigned*)&g_barGen == gen) { __nanosleep(64); }
        }
        __threadfence();        // acquire
    }
    __syncthreads();
}

// ---------------- weight pre-swizzle: B(n,k) -> fragment-native tf32 ----------------
template<class BL>
__global__ void swz_k(int boff, int N, int K, BL bl) {
    int idx = blockIdx.x * 256 + threadIdx.x;
    if (idx >= N*K) return;
    int n = idx / K, k = idx % K;
    int KTT = K >> 3;
    uint32_t* d = (uint32_t*)(g_Bswz + boff);
    int off = (((n>>3)*KTT + (k>>3))*32 + ((n&7)*4 + (k&3)))*2 + ((k>>2)&1);
    d[off] = f2tf(bl(n, k));
}

// ------------- tf32 GEMM tile (device fn): pre-swizzled A via smem, B direct LDG -------------
// BM must be 64 (smem buffer fixed at 2*512 uint4). BK = 32 (KT = 4 k8-tiles).
template<int BM,int BN,int WM,int WN,class EP>
__device__ __forceinline__ void gemm_tile(int K, int aoff, int boff,
                                          int bm, int bn, int lin, EP ep,
                                          uint4* AsB, float* redB) {
    constexpr int WARPS_M = BM/WM, WARPS_N = BN/WN;
    static_assert(WARPS_M*WARPS_N == 8, "need 8 warps");
    constexpr int MI = WM/16, NI = WN/8;
    constexpr int KT = 4;
    constexpr int TILE4 = (BM/16)*KT*32;   // 512 for BM=64
    constexpr int CP = TILE4/256;

    const int KTT = K >> 3;
    const int tid = threadIdx.x, lane = tid & 31, wid = tid >> 5;
    const int wm = (wid % WARPS_M)*WM, wn = (wid / WARPS_M)*WN;
    const int gid = lane >> 2, tig = lane & 3;
    const int mtBase = bm >> 4;
    const int ntBase = (bn + wn) >> 3;
    const int wmt = wm >> 4;

    const uint4* __restrict__ Ag = (const uint4*)(ASWZ_W + aoff);
    const uint2* __restrict__ Bg = g_Bswz + boff;

    float acc[MI][NI][4];
    #pragma unroll
    for (int mi = 0; mi < MI; mi++)
        #pragma unroll
        for (int ni = 0; ni < NI; ni++)
            #pragma unroll
            for (int c = 0; c < 4; c++) acc[mi][ni][c] = 0.f;

    uint4 ar[CP];
    auto ldA = [&](int kt0) {
        #pragma unroll
        for (int i = 0; i < CP; i++) {
            int e = tid + i*256;
            int mtl = e / (KT*32), rem = e % (KT*32);
            ar[i] = Ag[((mtBase + mtl)*KTT + kt0 + rem/32)*32 + (rem & 31)];
        }
    };
    auto stA = [&](int buf) {
        #pragma unroll
        for (int i = 0; i < CP; i++) AsB[buf*TILE4 + tid + i*256] = ar[i];
    };

    ldA(0); stA(0);
    __syncthreads();

    int cur = 0;
    for (int kt0 = 0; kt0 < KTT; kt0 += KT) {
        const bool more = (kt0 + KT) < KTT;
        uint2 bf[NI][KT];
        #pragma unroll
        for (int ni = 0; ni < NI; ni++)
            #pragma unroll
            for (int kk = 0; kk < KT; kk++)
                bf[ni][kk] = Bg[((ntBase + ni)*KTT + kt0 + kk)*32 + lane];
        if (more) ldA(kt0 + KT);

        #pragma unroll
        for (int kk = 0; kk < KT; kk++) {
            uint4 av[MI];
            #pragma unroll
            for (int mi = 0; mi < MI; mi++)
                av[mi] = AsB[cur*TILE4 + ((wmt + mi)*KT + kk)*32 + lane];
            #pragma unroll
            for (int mi = 0; mi < MI; mi++)
                #pragma unroll
                for (int ni = 0; ni < NI; ni++)
                    asm volatile(
                        "mma.sync.aligned.m16n8k8.row.col.f32.tf32.tf32.f32 "
                        "{%0,%1,%2,%3}, {%4,%5,%6,%7}, {%8,%9}, {%0,%1,%2,%3};"
                        : "+f"(acc[mi][ni][0]), "+f"(acc[mi][ni][1]),
                          "+f"(acc[mi][ni][2]), "+f"(acc[mi][ni][3])
                        : "r"(av[mi].x), "r"(av[mi].y), "r"(av[mi].z), "r"(av[mi].w),
                          "r"(bf[ni][kk].x), "r"(bf[ni][kk].y));
        }
        if (more) stA(cur ^ 1);
        __syncthreads();
        cur ^= 1;
    }

    float rsum = 0.f;
    #pragma unroll
    for (int mi = 0; mi < MI; mi++) {
        #pragma unroll
        for (int ni = 0; ni < NI; ni++) {
            int gm0 = bm + wm + mi*16 + gid;
            int gn0 = bn + wn + ni*8 + tig*2;
            rsum += ep(gm0,     gn0,     acc[mi][ni][0]);
            rsum += ep(gm0,     gn0 + 1, acc[mi][ni][1]);
            rsum += ep(gm0 + 8, gn0,     acc[mi][ni][2]);
            rsum += ep(gm0 + 8, gn0 + 1, acc[mi][ni][3]);
        }
    }

    if constexpr (EP::RED) {
        redB[tid] = rsum;
        __syncthreads();
        for (int s = 128; s > 0; s >>= 1) {
            if (tid < s) redB[tid] += redB[tid + s];
            __syncthreads();
        }
        if (tid == 0) ep.store_partial(lin, redB[0]);
        __syncthreads();
    }
}

// standalone GEMM (prologue P1/P2)
template<int BM,int BN,int WM,int WN,class EP>
__global__ __launch_bounds__(256, 2)
void tgemm4_k(int K, int aoff, int boff, EP ep) {
    __shared__ uint4 As[2*512];
    __shared__ float red[256];
    gemm_tile<BM,BN,WM,WN>(K, aoff, boff, blockIdx.y*BM, blockIdx.x*BN,
                           blockIdx.y*gridDim.x + blockIdx.x, ep, As, red);
}

// ---------------- B-side scalar loaders (used only by swz_k) ----------------

struct BL_P1 {
    const float* Wdh;
    __device__ float operator()(int n, int k) const { return Wdh[n*FV + k]; }
};
struct BL_P2 {
    const float* Wwc;
    __device__ float operator()(int n, int k) const { return Wwc[n*(2*FV) + k]; }
};
struct BL_G1 {
    const float* Wh; const float* Whh;
    __device__ float operator()(int n, int k) const {
        return (n < FV) ? Wh[n*HV + k] : Whh[(n - FV)*HV + k];
    }
};
struct BL_G2 {
    const float* Wfr;
    __device__ float operator()(int n, int k) const {
        return (n == k) ? 0.f : Wfr[n*FV + k];
    }
};
struct BL_G3 {
    const float* Wih;
    __device__ float operator()(int n, int k) const { return Wih[n*(2*FV) + k]; }
};

// ---------------- A-side pre-swizzle kernels ----------------

__global__ void swzA_P1_k(const float* __restrict__ deltas) {
    int idx = blockIdx.x * 256 + threadIdx.x;   // 32768*256
    int m = idx >> 8, k = idx & 255;
    int t = m >> 9, b = m & 511;
    ASWZ_W[AOFF_P1 + aidx(m, k, 32)] = f2tf(deltas[(b*TV + t)*FV + k]);
}

__global__ void swzA_P2_k(const float* __restrict__ deltas, const float* __restrict__ mask,
                          const float* __restrict__ Wdx, const float* __restrict__ bdx) {
    int idx = blockIdx.x * 256 + threadIdx.x;   // 32768*512
    int m = idx >> 9, k = idx & 511;
    int t = m >> 9, b = m & 511;
    float v;
    if (k < FV) {
        float d = deltas[(b*TV + t)*FV + k];
        v = expf(-fmaxf(d * Wdx[k*FV + k] + bdx[k], 0.f));
    } else {
        v = mask[(b*TV + t)*FV + (k - FV)];
    }
    ASWZ_W[AOFF_P2 + aidx(m, k, 64)] = f2tf(v);
}

__global__ void swzA_G3m_k(const float* __restrict__ mask) {
    int idx = blockIdx.x * 256 + threadIdx.x;   // 64*512*256
    int t = idx >> 17, b = (idx >> 8) & 511, f = idx & 255;
    ASWZ_W[AOFF_G3 + t*AG3_STRIDE + aidx(b, FV + f, 64)] =
        f2tf(mask[(b*TV + t)*FV + f]);
}

// h init: plain h0 + swizzled h0*gammaH[0] (run after P1 GEMM)
__global__ void hAinit_k(const float* __restrict__ h0) {
    int idx = blockIdx.x * 256 + threadIdx.x;   // B*H
    int b = idx >> 10, j = idx & 1023;
    float h = h0[idx];
    g_h[idx] = h;
    ASWZ_W[AOFF_G1 + aidx(b, j, 128)] = f2tf(h * g_gammaH[idx]);
}

// ---------------- epilogues ----------------

struct EP_P1 {
    const float* bdh;
    static constexpr bool RED = false;
    __device__ float operator()(int m, int n, float v) const {
        g_gammaH[(size_t)m*HV + n] = expf(-fmaxf(v + bdh[n], 0.f));
        return 0.f;
    }
    __device__ void store_partial(int, float) const {}
};
struct EP_P2 {
    const float* bwc;
    static constexpr bool RED = false;
    __device__ float operator()(int m, int n, float v) const {
        g_beta[(size_t)m*FV + n] = v + bwc[n];
        return 0.f;
    }
    __device__ void store_partial(int, float) const {}
};
struct EP_G1 {
    const float* bh; const float* bhh; const float* x; const float* mask; int t;
    static constexpr bool RED = false;
    __device__ float operator()(int m, int n, float v) const {
        if (n < FV) {
            float xh = v + bh[n];
            g_xh[m*FV + n] = xh;
            int idx = (m*TV + t)*FV + n;
            float mt = mask[idx];
            float xr = mt * x[idx] + (1.f - mt) * xh;
            ASWZ_W[AOFF_G2 + aidx(m, n, 32)] = f2tf(xr);
        } else {
            g_gh[m*3*HV + (n - FV)] = v + bhh[n - FV];
        }
        return 0.f;
    }
    __device__ void store_partial(int, float) const {}
};
struct EP_G2 {
    const float* bfr; const float* x; const float* mask;
    float* rec; float* ximp; int t;
    static constexpr bool RED = true;
    __device__ float operator()(int m, int n, float v) const {
        float xu = v + bfr[n];
        float xh = g_xh[m*FV + n];
        float be = g_beta[(size_t)t*BV*FV + m*FV + n];
        float xc = be * xu + (1.f - be) * xh;
        int idx = (m*TV + t)*FV + n;
        float mt = mask[idx], xt = x[idx];
        rec[idx]  = xc;
        float xi = mt * xt + (1.f - mt) * xc;
        ximp[idx] = xi;
        ASWZ_W[AOFF_G3 + t*AG3_STRIDE + aidx(m, n, 64)] = f2tf(xi);
        return fabsf(xc - xt) * mt;
    }
    __device__ void store_partial(int lin, float v) const {
        g_lossPart[t*NB2 + lin] = v;
    }
};
struct EP_G3 {
    const float* bih;
    static constexpr bool RED = false;
    __device__ float operator()(int m, int n, float v) const {
        g_gi[m*3*HV + n] = v + bih[n];
        return 0.f;
    }
    __device__ void store_partial(int, float) const {}
};

// ---------------- persistent fused loop kernel ----------------
__global__ __launch_bounds__(256, 2)
void loop_k(const float* __restrict__ x, const float* __restrict__ mask,
            const float* __restrict__ bh, const float* __restrict__ bhh,
            const float* __restrict__ bfr, const float* __restrict__ bih,
            float* __restrict__ rec, float* __restrict__ ximp,
            float* __restrict__ hfin, float* __restrict__ out) {
    __shared__ uint4 As[2*512];
    __shared__ float red[256];
    const int bid = blockIdx.x;
    const int tid = threadIdx.x;

    for (int t = 0; t < TV; t++) {
        // ---- G1: [x_h | gh], 26 x 8 = 208 tiles ----
        if (bid < 208) {
            int xx = bid % 26, yy = bid / 26;
            gemm_tile<64,128,32,32>(HV, AOFF_G1, BOFF_G1, yy*64, xx*128, bid,
                                    EP_G1{bh, bhh, x, mask, t}, As, red);
        }
        gridsync();

        // ---- G2: 4 x 8 = 32 tiles ----
        if (bid < 32) {
            int xx = bid % 4, yy = bid / 4;
            gemm_tile<64,64,32,16>(FV, AOFF_G2, BOFF_G2, yy*64, xx*64, bid,
                                   EP_G2{bfr, x, mask, rec, ximp, t}, As, red);
        }
        gridsync();

        // ---- G3: 24 x 8 = 192 tiles ----
        if (bid < 192) {
            int xx = bid % 24, yy = bid / 24;
            gemm_tile<64,128,32,32>(2*FV, AOFF_G3 + t*AG3_STRIDE, BOFF_G3,
                                    yy*64, xx*128, bid, EP_G3{bih}, As, red);
        }
        gridsync();

        // ---- GRU elementwise ----
        for (int idx = bid*256 + tid; idx < BV*HV; idx += PGRID*256) {
            int b = idx >> 10, j = idx & 1023;
            float hd = g_h[idx] * g_gammaH[(size_t)t*BV*HV + idx];
            int base = b*3*HV + j;
            float r = 1.f / (1.f + expf(-(g_gi[base]        + g_gh[base])));
            float z = 1.f / (1.f + expf(-(g_gi[base + HV]   + g_gh[base + HV])));
            float n = tanhf(g_gi[base + 2*HV] + r * g_gh[base + 2*HV]);
            float hn = (1.f - z) * n + z * hd;
            g_h[idx] = hn;
            if (t + 1 < TV)
                ASWZ_W[AOFF_G1 + aidx(b, j, 128)] =
                    f2tf(hn * g_gammaH[(size_t)(t+1)*BV*HV + idx]);
            else
                hfin[idx] = hn;
        }
        gridsync();
    }

    // ---- final loss reduction (block 0) ----
    if (bid == 0 && tid < TV) {
        float acc = 0.f;
        for (int i = 0; i < NB2; i++) acc += g_lossPart[tid*NB2 + i];
        red[tid] = acc / (g_msum[tid] + 1e-12f);
        __syncwarp();
        if (tid == 0) {
            float L = 0.f;
            for (int i = 0; i < TV; i++) L += red[i];
            out[OFF_LOSS]     = L;
            out[OFF_LOSS + 1] = 0.f;  // kl_loss
        }
    }
}

// ---------------- elementwise prologue kernels ----------------

__global__ void msum_k(const float* __restrict__ mask) {
    int t = blockIdx.x;
    float s = 0.f;
    for (int i = threadIdx.x; i < BV*FV; i += 256) {
        int b = i >> 8, f = i & 255;
        s += mask[(b*TV + t)*FV + f];
    }
    __shared__ float red[256];
    red[threadIdx.x] = s;
    __syncthreads();
    for (int st = 128; st > 0; st >>= 1) {
        if (threadIdx.x < st) red[threadIdx.x] += red[threadIdx.x + st];
        __syncthreads();
    }
    if (threadIdx.x == 0) g_msum[t] = red[0];
}

// ---------------- launch ----------------

extern "C" void kernel_launch(void* const* d_in, const int* in_sizes, int n_in,
                              void* d_out, int out_size) {
    const float* x      = (const float*)d_in[0];
    const float* mask   = (const float*)d_in[1];
    const float* deltas = (const float*)d_in[2];
    const float* h0     = (const float*)d_in[3];
    const float* Wdh    = (const float*)d_in[4];
    const float* bdh    = (const float*)d_in[5];
    const float* Wdx    = (const float*)d_in[6];
    const float* bdx    = (const float*)d_in[7];
    const float* Wh     = (const float*)d_in[8];
    const float* bh     = (const float*)d_in[9];
    const float* Wfr    = (const float*)d_in[10];
    const float* bfr    = (const float*)d_in[11];
    const float* Wwc    = (const float*)d_in[12];
    const float* bwc    = (const float*)d_in[13];
    const float* Wih    = (const float*)d_in[14];
    const float* bih    = (const float*)d_in[15];
    const float* Whh    = (const float*)d_in[16];
    const float* bhh    = (const float*)d_in[17];

    float* out      = (float*)d_out;
    float* ximp_out = out;
    float* rec_out  = out + OFF_REC;
    float* hfin     = out + OFF_HFIN;

    msum_k<<<TV, 256>>>(mask);

    // Pre-swizzle weights (B operands)
    swz_k<<<(3328*1024)/256, 256>>>(BOFF_G1, 3328, 1024, BL_G1{Wh, Whh});
    swz_k<<<(3072*512 )/256, 256>>>(BOFF_G3, 3072, 512,  BL_G3{Wih});
    swz_k<<<(256*256  )/256, 256>>>(BOFF_G2, 256,  256,  BL_G2{Wfr});
    swz_k<<<(1024*256 )/256, 256>>>(BOFF_P1, 1024, 256,  BL_P1{Wdh});
    swz_k<<<(256*512  )/256, 256>>>(BOFF_P2, 256,  512,  BL_P2{Wwc});

    // Pre-swizzle A operands for P1/P2 and G3 mask half
    swzA_P1_k<<<(32768*256)/256, 256>>>(deltas);
    swzA_P2_k<<<(32768*512)/256, 256>>>(deltas, mask, Wdx, bdx);
    swzA_G3m_k<<<(TV*BV*FV)/256, 256>>>(mask);

    // P1: gammaH, M=32768, N=1024, K=256
    tgemm4_k<64,128,32,32><<<dim3(1024/128, 32768/64), 256>>>(
        FV, AOFF_P1, BOFF_P1, EP_P1{bdh});

    // h init (needs gammaH[0])
    hAinit_k<<<(BV*HV)/256, 256>>>(h0);

    // P2: beta, M=32768, N=256, K=512
    tgemm4_k<64,128,32,32><<<dim3(256/128, 32768/64), 256>>>(
        2*FV, AOFF_P2, BOFF_P2, EP_P2{bwc});

    // Persistent fused recurrence (all 64 steps + final loss)
    loop_k<<<PGRID, 256>>>(x, mask, bh, bhh, bfr, bih,
                           rec_out, ximp_out, hfin, out);
}

// round 10
// speedup vs baseline: 1.0037x; 1.0037x over previous
#include <cuda_runtime.h>
#include <math.h>
#include <stdint.h>

// Problem constants
#define BV 512
#define TV 64
#define FV 256
#define HV 1024

// Output layout: x_imp [B,T,F] | reconstruction [B,T,F] | h_fin [B,H] | x_loss | kl_loss
#define OFF_REC   (BV*TV*FV)
#define OFF_HFIN  (2*BV*TV*FV)
#define OFF_LOSS  (2*BV*TV*FV + BV*HV)

#define NB2 32   // loss partial tiles per step

// ---------------- scratch ----------------
__device__ float g_h[BV*HV];
__device__ float g_xh[BV*FV];
__device__ float g_gh[BV*3*HV];
__device__ float g_gi[BV*3*HV];
__device__ float g_gammaH[(size_t)TV*BV*HV];
__device__ float g_beta[(size_t)TV*BV*FV];
__device__ float g_msum[TV];
__device__ float g_lossPart[TV*NB2];

// ---- pre-swizzled tf32 B (weights), uint2 fragment granularity ----
#define SZ2(N,K) ((N)*(K)/2)
#define BOFF_G1 0
#define BOFF_G3 (BOFF_G1 + SZ2(3328,1024))
#define BOFF_G2 (BOFF_G3 + SZ2(3072,512))
#define BOFF_P1 (BOFF_G2 + SZ2(256,256))
#define BOFF_P2 (BOFF_P1 + SZ2(1024,256))
#define BSWZ_TOTAL (BOFF_P2 + SZ2(256,512))
__device__ uint2 g_Bswz[BSWZ_TOTAL];

// ---- pre-swizzled tf32 A (activations), uint32 words, 16B-aligned ----
#define AOFF_G1 0                                   // 512x1024
#define AOFF_G2 (AOFF_G1 + BV*HV)                   // 512x256
#define AOFF_G3 (AOFF_G2 + BV*FV)                   // 64 slices of 512x512
#define AG3_STRIDE (BV*2*FV)
#define AOFF_P1 (AOFF_G3 + TV*AG3_STRIDE)           // 32768x256
#define AOFF_P2 (AOFF_P1 + TV*BV*FV)                // 32768x512
#define ASWZ_TOTAL (AOFF_P2 + TV*BV*2*FV)
__device__ uint4 g_Aswz4[ASWZ_TOTAL/4];
#define ASWZ_W ((uint32_t*)g_Aswz4)

__device__ __forceinline__ uint32_t f2tf(float f) {
    uint32_t r;
    asm("cvt.rna.tf32.f32 %0, %1;" : "=r"(r) : "f"(f));
    return r;
}

// word index of element (m,k) in fragment-native A layout (KTT = K/8)
__device__ __forceinline__ int aidx(int m, int k, int KTT) {
    int r = m & 15, c = k & 7;
    return (((m >> 4)*KTT + (k >> 3))*32 + (r & 7)*4 + (c & 3))*4
           + (r >> 3) + (((k >> 2) & 1) << 1);
}

// ---------------- weight pre-swizzle: B(n,k) -> fragment-native tf32 ----------------
template<class BL>
__global__ void swz_k(int boff, int N, int K, BL bl) {
    int idx = blockIdx.x * 256 + threadIdx.x;
    if (idx >= N*K) return;
    int n = idx / K, k = idx % K;
    int KTT = K >> 3;
    uint32_t* d = (uint32_t*)(g_Bswz + boff);
    int off = (((n>>3)*KTT + (k>>3))*32 + ((n&7)*4 + (k&3)))*2 + ((k>>2)&1);
    d[off] = f2tf(bl(n, k));
}

// ------------- tf32 GEMM tile (device fn): pre-swizzled A via smem, B direct LDG -------------
// BM must be 64 (smem buffer fixed at 2*512 uint4). BK = 32 (KT = 4 k8-tiles).
template<int BM,int BN,int WM,int WN,class EP>
__device__ __forceinline__ void gemm_tile(int K, int aoff, int boff,
                                          int bm, int bn, int lin, EP ep,
                                          uint4* AsB, float* redB) {
    constexpr int WARPS_M = BM/WM, WARPS_N = BN/WN;
    static_assert(WARPS_M*WARPS_N == 8, "need 8 warps");
    constexpr int MI = WM/16, NI = WN/8;
    constexpr int KT = 4;
    constexpr int TILE4 = (BM/16)*KT*32;   // 512 for BM=64
    constexpr int CP = TILE4/256;

    const int KTT = K >> 3;
    const int tid = threadIdx.x, lane = tid & 31, wid = tid >> 5;
    const int wm = (wid % WARPS_M)*WM, wn = (wid / WARPS_M)*WN;
    const int gid = lane >> 2, tig = lane & 3;
    const int mtBase = bm >> 4;
    const int ntBase = (bn + wn) >> 3;
    const int wmt = wm >> 4;

    const uint4* __restrict__ Ag = (const uint4*)(ASWZ_W + aoff);
    const uint2* __restrict__ Bg = g_Bswz + boff;

    float acc[MI][NI][4];
    #pragma unroll
    for (int mi = 0; mi < MI; mi++)
        #pragma unroll
        for (int ni = 0; ni < NI; ni++)
            #pragma unroll
            for (int c = 0; c < 4; c++) acc[mi][ni][c] = 0.f;

    uint4 ar[CP];
    auto ldA = [&](int kt0) {
        #pragma unroll
        for (int i = 0; i < CP; i++) {
            int e = tid + i*256;
            int mtl = e / (KT*32), rem = e % (KT*32);
            ar[i] = Ag[((mtBase + mtl)*KTT + kt0 + rem/32)*32 + (rem & 31)];
        }
    };
    auto stA = [&](int buf) {
        #pragma unroll
        for (int i = 0; i < CP; i++) AsB[buf*TILE4 + tid + i*256] = ar[i];
    };

    ldA(0); stA(0);
    __syncthreads();

    int cur = 0;
    for (int kt0 = 0; kt0 < KTT; kt0 += KT) {
        const bool more = (kt0 + KT) < KTT;
        uint2 bf[NI][KT];
        #pragma unroll
        for (int ni = 0; ni < NI; ni++)
            #pragma unroll
            for (int kk = 0; kk < KT; kk++)
                bf[ni][kk] = Bg[((ntBase + ni)*KTT + kt0 + kk)*32 + lane];
        if (more) ldA(kt0 + KT);

        #pragma unroll
        for (int kk = 0; kk < KT; kk++) {
            uint4 av[MI];
            #pragma unroll
            for (int mi = 0; mi < MI; mi++)
                av[mi] = AsB[cur*TILE4 + ((wmt + mi)*KT + kk)*32 + lane];
            #pragma unroll
            for (int mi = 0; mi < MI; mi++)
                #pragma unroll
                for (int ni = 0; ni < NI; ni++)
                    asm volatile(
                        "mma.sync.aligned.m16n8k8.row.col.f32.tf32.tf32.f32 "
                        "{%0,%1,%2,%3}, {%4,%5,%6,%7}, {%8,%9}, {%0,%1,%2,%3};"
                        : "+f"(acc[mi][ni][0]), "+f"(acc[mi][ni][1]),
                          "+f"(acc[mi][ni][2]), "+f"(acc[mi][ni][3])
                        : "r"(av[mi].x), "r"(av[mi].y), "r"(av[mi].z), "r"(av[mi].w),
                          "r"(bf[ni][kk].x), "r"(bf[ni][kk].y));
        }
        if (more) stA(cur ^ 1);
        __syncthreads();
        cur ^= 1;
    }

    float rsum = 0.f;
    #pragma unroll
    for (int mi = 0; mi < MI; mi++) {
        #pragma unroll
        for (int ni = 0; ni < NI; ni++) {
            int gm0 = bm + wm + mi*16 + gid;
            int gn0 = bn + wn + ni*8 + tig*2;
            rsum += ep(gm0,     gn0,     acc[mi][ni][0]);
            rsum += ep(gm0,     gn0 + 1, acc[mi][ni][1]);
            rsum += ep(gm0 + 8, gn0,     acc[mi][ni][2]);
            rsum += ep(gm0 + 8, gn0 + 1, acc[mi][ni][3]);
        }
    }

    if constexpr (EP::RED) {
        redB[tid] = rsum;
        __syncthreads();
        for (int s = 128; s > 0; s >>= 1) {
            if (tid < s) redB[tid] += redB[tid + s];
            __syncthreads();
        }
        if (tid == 0) ep.store_partial(lin, redB[0]);
        __syncthreads();
    }
}

// standalone GEMM
template<int BM,int BN,int WM,int WN,class EP>
__global__ __launch_bounds__(256, 2)
void tgemm4_k(int K, int aoff, int boff, EP ep) {
    __shared__ uint4 As[2*512];
    __shared__ float red[256];
    gemm_tile<BM,BN,WM,WN>(K, aoff, boff, blockIdx.y*BM, blockIdx.x*BN,
                           blockIdx.y*gridDim.x + blockIdx.x, ep, As, red);
}

// ---------------- B-side scalar loaders (used only by swz_k) ----------------

struct BL_P1 {
    const float* Wdh;
    __device__ float operator()(int n, int k) const { return Wdh[n*FV + k]; }
};
struct BL_P2 {
    const float* Wwc;
    __device__ float operator()(int n, int k) const { return Wwc[n*(2*FV) + k]; }
};
struct BL_G1 {
    const float* Wh; const float* Whh;
    __device__ float operator()(int n, int k) const {
        return (n < FV) ? Wh[n*HV + k] : Whh[(n - FV)*HV + k];
    }
};
struct BL_G2 {
    const float* Wfr;
    __device__ float operator()(int n, int k) const {
        return (n == k) ? 0.f : Wfr[n*FV + k];
    }
};
struct BL_G3 {
    const float* Wih;
    __device__ float operator()(int n, int k) const { return Wih[n*(2*FV) + k]; }
};

// ---------------- A-side pre-swizzle kernels ----------------

__global__ void swzA_P1_k(const float* __restrict__ deltas) {
    int idx = blockIdx.x * 256 + threadIdx.x;   // 32768*256
    int m = idx >> 8, k = idx & 255;
    int t = m >> 9, b = m & 511;
    ASWZ_W[AOFF_P1 + aidx(m, k, 32)] = f2tf(deltas[(b*TV + t)*FV + k]);
}

__global__ void swzA_P2_k(const float* __restrict__ deltas, const float* __restrict__ mask,
                          const float* __restrict__ Wdx, const float* __restrict__ bdx) {
    int idx = blockIdx.x * 256 + threadIdx.x;   // 32768*512
    int m = idx >> 9, k = idx & 511;
    int t = m >> 9, b = m & 511;
    float v;
    if (k < FV) {
        float d = deltas[(b*TV + t)*FV + k];
        v = expf(-fmaxf(d * Wdx[k*FV + k] + bdx[k], 0.f));
    } else {
        v = mask[(b*TV + t)*FV + (k - FV)];
    }
    ASWZ_W[AOFF_P2 + aidx(m, k, 64)] = f2tf(v);
}

__global__ void swzA_G3m_k(const float* __restrict__ mask) {
    int idx = blockIdx.x * 256 + threadIdx.x;   // 64*512*256
    int t = idx >> 17, b = (idx >> 8) & 511, f = idx & 255;
    ASWZ_W[AOFF_G3 + t*AG3_STRIDE + aidx(b, FV + f, 64)] =
        f2tf(mask[(b*TV + t)*FV + f]);
}

// h init: plain h0 + swizzled h0*gammaH[0] (run after P1 GEMM)
__global__ void hAinit_k(const float* __restrict__ h0) {
    int idx = blockIdx.x * 256 + threadIdx.x;   // B*H
    int b = idx >> 10, j = idx & 1023;
    float h = h0[idx];
    g_h[idx] = h;
    ASWZ_W[AOFF_G1 + aidx(b, j, 128)] = f2tf(h * g_gammaH[idx]);
}

// ---------------- epilogues ----------------

struct EP_P1 {
    const float* bdh;
    static constexpr bool RED = false;
    __device__ float operator()(int m, int n, float v) const {
        g_gammaH[(size_t)m*HV + n] = expf(-fmaxf(v + bdh[n], 0.f));
        return 0.f;
    }
    __device__ void store_partial(int, float) const {}
};
struct EP_P2 {
    const float* bwc;
    static constexpr bool RED = false;
    __device__ float operator()(int m, int n, float v) const {
        g_beta[(size_t)m*FV + n] = v + bwc[n];
        return 0.f;
    }
    __device__ void store_partial(int, float) const {}
};
struct EP_G1 {
    const float* bh; const float* bhh; const float* x; const float* mask; int t;
    static constexpr bool RED = false;
    __device__ float operator()(int m, int n, float v) const {
        if (n < FV) {
            float xh = v + bh[n];
            g_xh[m*FV + n] = xh;
            int idx = (m*TV + t)*FV + n;
            float mt = mask[idx];
            float xr = mt * x[idx] + (1.f - mt) * xh;
            ASWZ_W[AOFF_G2 + aidx(m, n, 32)] = f2tf(xr);
        } else {
            g_gh[m*3*HV + (n - FV)] = v + bhh[n - FV];
        }
        return 0.f;
    }
    __device__ void store_partial(int, float) const {}
};
struct EP_G2 {
    const float* bfr; const float* x; const float* mask;
    float* rec; float* ximp; int t;
    static constexpr bool RED = true;
    __device__ float operator()(int m, int n, float v) const {
        float xu = v + bfr[n];
        float xh = g_xh[m*FV + n];
        float be = g_beta[(size_t)t*BV*FV + m*FV + n];
        float xc = be * xu + (1.f - be) * xh;
        int idx = (m*TV + t)*FV + n;
        float mt = mask[idx], xt = x[idx];
        rec[idx]  = xc;
        float xi = mt * xt + (1.f - mt) * xc;
        ximp[idx] = xi;
        ASWZ_W[AOFF_G3 + t*AG3_STRIDE + aidx(m, n, 64)] = f2tf(xi);
        return fabsf(xc - xt) * mt;
    }
    __device__ void store_partial(int lin, float v) const {
        g_lossPart[t*NB2 + lin] = v;
    }
};
struct EP_G3 {
    const float* bih;
    static constexpr bool RED = false;
    __device__ float operator()(int m, int n, float v) const {
        g_gi[m*3*HV + n] = v + bih[n];
        return 0.f;
    }
    __device__ void store_partial(int, float) const {}
};

// ---------------- combined big kernel: G1-gh (192 tiles) + G3 (192 tiles) ----------------
__global__ __launch_bounds__(256, 2)
void big_k(int aoffG3, EP_G1 epg1, EP_G3 epg3) {
    __shared__ uint4 As[2*512];
    __shared__ float red[256];
    const int bid = blockIdx.x;
    if (bid < 192) {
        // G1-gh: N in [256, 3328), K = 1024
        int xx = bid % 24, yy = bid / 24;
        gemm_tile<64,128,32,32>(HV, AOFF_G1, BOFF_G1,
                                yy*64, 256 + xx*128, bid, epg1, As, red);
    } else {
        // G3: N = 3072, K = 512
        int b2 = bid - 192;
        int xx = b2 % 24, yy = b2 / 24;
        gemm_tile<64,128,32,32>(2*FV, aoffG3, BOFF_G3,
                                yy*64, xx*128, b2, epg3, As, red);
    }
}

// ---------------- elementwise kernels ----------------

__global__ void msum_k(const float* __restrict__ mask) {
    int t = blockIdx.x;
    float s = 0.f;
    for (int i = threadIdx.x; i < BV*FV; i += 256) {
        int b = i >> 8, f = i & 255;
        s += mask[(b*TV + t)*FV + f];
    }
    __shared__ float red[256];
    red[threadIdx.x] = s;
    __syncthreads();
    for (int st = 128; st > 0; st >>= 1) {
        if (threadIdx.x < st) red[threadIdx.x] += red[threadIdx.x + st];
        __syncthreads();
    }
    if (threadIdx.x == 0) g_msum[t] = red[0];
}

// GRU update; also produces next step's swizzled A (h_new * gammaH[t+1])
__global__ void gru_k(int t, float* __restrict__ hfin) {
    int idx = blockIdx.x * blockDim.x + threadIdx.x;  // B*H
    int b = idx >> 10, j = idx & 1023;
    float hd = g_h[idx] * g_gammaH[(size_t)t*BV*HV + idx];
    int base = b*3*HV + j;
    float r = 1.f / (1.f + expf(-(g_gi[base]        + g_gh[base])));
    float z = 1.f / (1.f + expf(-(g_gi[base + HV]   + g_gh[base + HV])));
    float n = tanhf(g_gi[base + 2*HV] + r * g_gh[base + 2*HV]);
    float hn = (1.f - z) * n + z * hd;
    g_h[idx] = hn;
    if (t + 1 < TV)
        ASWZ_W[AOFF_G1 + aidx(b, j, 128)] =
            f2tf(hn * g_gammaH[(size_t)(t+1)*BV*HV + idx]);
    if (hfin) hfin[idx] = hn;
}

__global__ void final_k(float* __restrict__ out) {
    __shared__ float s[TV];
    int t = threadIdx.x;  // 64 threads
    float acc = 0.f;
    for (int i = 0; i < NB2; i++) acc += g_lossPart[t*NB2 + i];
    s[t] = acc / (g_msum[t] + 1e-12f);
    __syncthreads();
    if (t == 0) {
        float L = 0.f;
        for (int i = 0; i < TV; i++) L += s[i];
        out[OFF_LOSS]     = L;
        out[OFF_LOSS + 1] = 0.f;  // kl_loss
    }
}

// ---------------- launch ----------------

extern "C" void kernel_launch(void* const* d_in, const int* in_sizes, int n_in,
                              void* d_out, int out_size) {
    const float* x      = (const float*)d_in[0];
    const float* mask   = (const float*)d_in[1];
    const float* deltas = (const float*)d_in[2];
    const float* h0     = (const float*)d_in[3];
    const float* Wdh    = (const float*)d_in[4];
    const float* bdh    = (const float*)d_in[5];
    const float* Wdx    = (const float*)d_in[6];
    const float* bdx    = (const float*)d_in[7];
    const float* Wh     = (const float*)d_in[8];
    const float* bh     = (const float*)d_in[9];
    const float* Wfr    = (const float*)d_in[10];
    const float* bfr    = (const float*)d_in[11];
    const float* Wwc    = (const float*)d_in[12];
    const float* bwc    = (const float*)d_in[13];
    const float* Wih    = (const float*)d_in[14];
    const float* bih    = (const float*)d_in[15];
    const float* Whh    = (const float*)d_in[16];
    const float* bhh    = (const float*)d_in[17];

    float* out      = (float*)d_out;
    float* ximp_out = out;
    float* rec_out  = out + OFF_REC;
    float* hfin     = out + OFF_HFIN;

    msum_k<<<TV, 256>>>(mask);

    // Pre-swizzle weights (B operands)
    swz_k<<<(3328*1024)/256, 256>>>(BOFF_G1, 3328, 1024, BL_G1{Wh, Whh});
    swz_k<<<(3072*512 )/256, 256>>>(BOFF_G3, 3072, 512,  BL_G3{Wih});
    swz_k<<<(256*256  )/256, 256>>>(BOFF_G2, 256,  256,  BL_G2{Wfr});
    swz_k<<<(1024*256 )/256, 256>>>(BOFF_P1, 1024, 256,  BL_P1{Wdh});
    swz_k<<<(256*512  )/256, 256>>>(BOFF_P2, 256,  512,  BL_P2{Wwc});

    // Pre-swizzle A operands for P1/P2 and G3 mask half
    swzA_P1_k<<<(32768*256)/256, 256>>>(deltas);
    swzA_P2_k<<<(32768*512)/256, 256>>>(deltas, mask, Wdx, bdx);
    swzA_G3m_k<<<(TV*BV*FV)/256, 256>>>(mask);

    // P1: gammaH, M=32768, N=1024, K=256
    tgemm4_k<64,128,32,32><<<dim3(1024/128, 32768/64), 256>>>(
        FV, AOFF_P1, BOFF_P1, EP_P1{bdh});

    // h init (needs gammaH[0])
    hAinit_k<<<(BV*HV)/256, 256>>>(h0);

    // P2: beta, M=32768, N=256, K=512
    tgemm4_k<64,128,32,32><<<dim3(256/128, 32768/64), 256>>>(
        2*FV, AOFF_P2, BOFF_P2, EP_P2{bwc});

    for (int t = 0; t < TV; t++) {
        // Phase 1: x_h slice of G1 only (N in [0,256), K=1024) -> 16 blocks
        tgemm4_k<64,128,32,32><<<dim3(2, 8), 256>>>(
            HV, AOFF_G1, BOFF_G1, EP_G1{bh, bhh, x, mask, t});

        // Phase 2: G2 (xu + combine/imputation/loss), 32 blocks
        tgemm4_k<64,64,32,16><<<dim3(4, 8), 256>>>(
            FV, AOFF_G2, BOFF_G2, EP_G2{bfr, x, mask, rec_out, ximp_out, t});

        // Phase 3: combined G1-gh (192 tiles, K=1024) + G3 (192 tiles, K=512)
        big_k<<<384, 256>>>(AOFF_G3 + t*AG3_STRIDE,
                            EP_G1{bh, bhh, x, mask, t}, EP_G3{bih});

        // Phase 4: GRU elementwise update (+ next step's swizzled A)
        gru_k<<<(BV*HV)/256, 256>>>(t, (t == TV-1) ? hfin : nullptr);
    }

    final_k<<<1, TV>>>(out);
}

// round 11
// speedup vs baseline: 1.0487x; 1.0448x over previous
#include <cuda_runtime.h>
#include <math.h>
#include <stdint.h>

// Problem constants
#define BV 512
#define TV 64
#define FV 256
#define HV 1024

// Output layout: x_imp [B,T,F] | reconstruction [B,T,F] | h_fin [B,H] | x_loss | kl_loss
#define OFF_REC   (BV*TV*FV)
#define OFF_HFIN  (2*BV*TV*FV)
#define OFF_LOSS  (2*BV*TV*FV + BV*HV)

#define NB2 32   // loss partial tiles per step

// ---------------- scratch ----------------
__device__ float g_h[BV*HV];
__device__ float g_xh[BV*FV];
__device__ float g_gh[BV*3*HV];
__device__ float g_gi[BV*3*HV];
__device__ float g_gammaH[(size_t)TV*BV*HV];
__device__ float g_beta[(size_t)TV*BV*FV];
__device__ float g_msum[TV];
__device__ float g_lossPart[TV*NB2];

// ---- pre-swizzled tf32 B (weights), uint2 fragment granularity ----
#define SZ2(N,K) ((N)*(K)/2)
#define BOFF_G1 0
#define BOFF_G3 (BOFF_G1 + SZ2(3328,1024))
#define BOFF_G2 (BOFF_G3 + SZ2(3072,512))
#define BOFF_P1 (BOFF_G2 + SZ2(256,256))
#define BOFF_P2 (BOFF_P1 + SZ2(1024,256))
#define BSWZ_TOTAL (BOFF_P2 + SZ2(256,512))
__device__ uint2 g_Bswz[BSWZ_TOTAL];

// ---- pre-swizzled tf32 A (activations), uint32 words, 16B-aligned ----
#define AOFF_G1 0                                   // 512x1024
#define AOFF_G2 (AOFF_G1 + BV*HV)                   // 512x256
#define AOFF_G3 (AOFF_G2 + BV*FV)                   // 64 slices of 512x512
#define AG3_STRIDE (BV*2*FV)
#define AOFF_P1 (AOFF_G3 + TV*AG3_STRIDE)           // 32768x256
#define AOFF_P2 (AOFF_P1 + TV*BV*FV)                // 32768x512
#define ASWZ_TOTAL (AOFF_P2 + TV*BV*2*FV)
__device__ uint4 g_Aswz4[ASWZ_TOTAL/4];
#define ASWZ_W ((uint32_t*)g_Aswz4)

__device__ __forceinline__ uint32_t f2tf(float f) {
    uint32_t r;
    asm("cvt.rna.tf32.f32 %0, %1;" : "=r"(r) : "f"(f));
    return r;
}

// word index of element (m,k) in fragment-native A layout (KTT = K/8)
__device__ __forceinline__ int aidx(int m, int k, int KTT) {
    int r = m & 15, c = k & 7;
    return (((m >> 4)*KTT + (k >> 3))*32 + (r & 7)*4 + (c & 3))*4
           + (r >> 3) + (((k >> 2) & 1) << 1);
}

// ---------------- weight pre-swizzle: B(n,k) -> fragment-native tf32 ----------------
template<class BL>
__global__ void swz_k(int boff, int N, int K, BL bl) {
    int idx = blockIdx.x * 256 + threadIdx.x;
    if (idx >= N*K) return;
    int n = idx / K, k = idx % K;
    int KTT = K >> 3;
    uint32_t* d = (uint32_t*)(g_Bswz + boff);
    int off = (((n>>3)*KTT + (k>>3))*32 + ((n&7)*4 + (k&3)))*2 + ((k>>2)&1);
    d[off] = f2tf(bl(n, k));
}

// ------------- tf32 GEMM tile: pre-swizzled A via smem, B double-buffered LDG -------------
// BM must be 64 (smem buffer fixed at 2*512 uint4). BK = 32 (KT = 4 k8-tiles).
template<int BM,int BN,int WM,int WN,class EP>
__device__ __forceinline__ void gemm_tile(int K, int aoff, int boff,
                                          int bm, int bn, int lin, EP ep,
                                          uint4* AsB, float* redB) {
    constexpr int WARPS_M = BM/WM, WARPS_N = BN/WN;
    static_assert(WARPS_M*WARPS_N == 8, "need 8 warps");
    constexpr int MI = WM/16, NI = WN/8;
    constexpr int KT = 4;
    constexpr int TILE4 = (BM/16)*KT*32;   // 512 for BM=64
    constexpr int CP = TILE4/256;

    const int KTT = K >> 3;
    const int tid = threadIdx.x, lane = tid & 31, wid = tid >> 5;
    const int wm = (wid % WARPS_M)*WM, wn = (wid / WARPS_M)*WN;
    const int gid = lane >> 2, tig = lane & 3;
    const int mtBase = bm >> 4;
    const int ntBase = (bn + wn) >> 3;
    const int wmt = wm >> 4;

    const uint4* __restrict__ Ag = (const uint4*)(ASWZ_W + aoff);
    const uint2* __restrict__ Bg = g_Bswz + boff;

    float acc[MI][NI][4];
    #pragma unroll
    for (int mi = 0; mi < MI; mi++)
        #pragma unroll
        for (int ni = 0; ni < NI; ni++)
            #pragma unroll
            for (int c = 0; c < 4; c++) acc[mi][ni][c] = 0.f;

    uint4 ar[CP];
    auto ldA = [&](int kt0) {
        #pragma unroll
        for (int i = 0; i < CP; i++) {
            int e = tid + i*256;
            int mtl = e / (KT*32), rem = e % (KT*32);
            ar[i] = Ag[((mtBase + mtl)*KTT + kt0 + rem/32)*32 + (rem & 31)];
        }
    };
    auto stA = [&](int buf) {
        #pragma unroll
        for (int i = 0; i < CP; i++) AsB[buf*TILE4 + tid + i*256] = ar[i];
    };

    uint2 bfc[NI][KT], bfn[NI][KT];
    auto ldB = [&](uint2 (&dst)[NI][KT], int kt0) {
        #pragma unroll
        for (int ni = 0; ni < NI; ni++)
            #pragma unroll
            for (int kk = 0; kk < KT; kk++)
                dst[ni][kk] = Bg[((ntBase + ni)*KTT + kt0 + kk)*32 + lane];
    };

    ldA(0); stA(0);
    ldB(bfc, 0);
    __syncthreads();

    int cur = 0;
    for (int kt0 = 0; kt0 < KTT; kt0 += KT) {
        const bool more = (kt0 + KT) < KTT;
        // prefetch next tile's A and B while computing current
        if (more) {
            ldB(bfn, kt0 + KT);
            ldA(kt0 + KT);
        }

        #pragma unroll
        for (int kk = 0; kk < KT; kk++) {
            uint4 av[MI];
            #pragma unroll
            for (int mi = 0; mi < MI; mi++)
                av[mi] = AsB[cur*TILE4 + ((wmt + mi)*KT + kk)*32 + lane];
            #pragma unroll
            for (int mi = 0; mi < MI; mi++)
                #pragma unroll
                for (int ni = 0; ni < NI; ni++)
                    asm volatile(
                        "mma.sync.aligned.m16n8k8.row.col.f32.tf32.tf32.f32 "
                        "{%0,%1,%2,%3}, {%4,%5,%6,%7}, {%8,%9}, {%0,%1,%2,%3};"
                        : "+f"(acc[mi][ni][0]), "+f"(acc[mi][ni][1]),
                          "+f"(acc[mi][ni][2]), "+f"(acc[mi][ni][3])
                        : "r"(av[mi].x), "r"(av[mi].y), "r"(av[mi].z), "r"(av[mi].w),
                          "r"(bfc[ni][kk].x), "r"(bfc[ni][kk].y));
        }
        if (more) {
            stA(cur ^ 1);
            #pragma unroll
            for (int ni = 0; ni < NI; ni++)
                #pragma unroll
                for (int kk = 0; kk < KT; kk++)
                    bfc[ni][kk] = bfn[ni][kk];
        }
        __syncthreads();
        cur ^= 1;
    }

    float rsum = 0.f;
    #pragma unroll
    for (int mi = 0; mi < MI; mi++) {
        #pragma unroll
        for (int ni = 0; ni < NI; ni++) {
            int gm0 = bm + wm + mi*16 + gid;
            int gn0 = bn + wn + ni*8 + tig*2;
            rsum += ep(gm0,     gn0,     acc[mi][ni][0]);
            rsum += ep(gm0,     gn0 + 1, acc[mi][ni][1]);
            rsum += ep(gm0 + 8, gn0,     acc[mi][ni][2]);
            rsum += ep(gm0 + 8, gn0 + 1, acc[mi][ni][3]);
        }
    }

    if constexpr (EP::RED) {
        redB[tid] = rsum;
        __syncthreads();
        for (int s = 128; s > 0; s >>= 1) {
            if (tid < s) redB[tid] += redB[tid + s];
            __syncthreads();
        }
        if (tid == 0) ep.store_partial(lin, redB[0]);
        __syncthreads();
    }
}

// standalone GEMM
template<int BM,int BN,int WM,int WN,class EP>
__global__ __launch_bounds__(256, 2)
void tgemm4_k(int K, int aoff, int boff, EP ep) {
    __shared__ uint4 As[2*512];
    __shared__ float red[256];
    gemm_tile<BM,BN,WM,WN>(K, aoff, boff, blockIdx.y*BM, blockIdx.x*BN,
                           blockIdx.y*gridDim.x + blockIdx.x, ep, As, red);
}

// ---------------- B-side scalar loaders (used only by swz_k) ----------------

struct BL_P1 {
    const float* Wdh;
    __device__ float operator()(int n, int k) const { return Wdh[n*FV + k]; }
};
struct BL_P2 {
    const float* Wwc;
    __device__ float operator()(int n, int k) const { return Wwc[n*(2*FV) + k]; }
};
struct BL_G1 {
    const float* Wh; const float* Whh;
    __device__ float operator()(int n, int k) const {
        return (n < FV) ? Wh[n*HV + k] : Whh[(n - FV)*HV + k];
    }
};
struct BL_G2 {
    const float* Wfr;
    __device__ float operator()(int n, int k) const {
        return (n == k) ? 0.f : Wfr[n*FV + k];
    }
};
struct BL_G3 {
    const float* Wih;
    __device__ float operator()(int n, int k) const { return Wih[n*(2*FV) + k]; }
};

// ---------------- A-side pre-swizzle kernels ----------------

__global__ void swzA_P1_k(const float* __restrict__ deltas) {
    int idx = blockIdx.x * 256 + threadIdx.x;   // 32768*256
    int m = idx >> 8, k = idx & 255;
    int t = m >> 9, b = m & 511;
    ASWZ_W[AOFF_P1 + aidx(m, k, 32)] = f2tf(deltas[(b*TV + t)*FV + k]);
}

__global__ void swzA_P2_k(const float* __restrict__ deltas, const float* __restrict__ mask,
                          const float* __restrict__ Wdx, const float* __restrict__ bdx) {
    int idx = blockIdx.x * 256 + threadIdx.x;   // 32768*512
    int m = idx >> 9, k = idx & 511;
    int t = m >> 9, b = m & 511;
    float v;
    if (k < FV) {
        float d = deltas[(b*TV + t)*FV + k];
        v = expf(-fmaxf(d * Wdx[k*FV + k] + bdx[k], 0.f));
    } else {
        v = mask[(b*TV + t)*FV + (k - FV)];
    }
    ASWZ_W[AOFF_P2 + aidx(m, k, 64)] = f2tf(v);
}

__global__ void swzA_G3m_k(const float* __restrict__ mask) {
    int idx = blockIdx.x * 256 + threadIdx.x;   // 64*512*256
    int t = idx >> 17, b = (idx >> 8) & 511, f = idx & 255;
    ASWZ_W[AOFF_G3 + t*AG3_STRIDE + aidx(b, FV + f, 64)] =
        f2tf(mask[(b*TV + t)*FV + f]);
}

// h init: plain h0 + swizzled h0*gammaH[0] (run after P1 GEMM)
__global__ void hAinit_k(const float* __restrict__ h0) {
    int idx = blockIdx.x * 256 + threadIdx.x;   // B*H
    int b = idx >> 10, j = idx & 1023;
    float h = h0[idx];
    g_h[idx] = h;
    ASWZ_W[AOFF_G1 + aidx(b, j, 128)] = f2tf(h * g_gammaH[idx]);
}

// ---------------- epilogues ----------------

struct EP_P1 {
    const float* bdh;
    static constexpr bool RED = false;
    __device__ float operator()(int m, int n, float v) const {
        g_gammaH[(size_t)m*HV + n] = expf(-fmaxf(v + bdh[n], 0.f));
        return 0.f;
    }
    __device__ void store_partial(int, float) const {}
};
struct EP_P2 {
    const float* bwc;
    static constexpr bool RED = false;
    __device__ float operator()(int m, int n, float v) const {
        g_beta[(size_t)m*FV + n] = v + bwc[n];
        return 0.f;
    }
    __device__ void store_partial(int, float) const {}
};
struct EP_G1 {
    const float* bh; const float* bhh; const float* x; const float* mask; int t;
    static constexpr bool RED = false;
    __device__ float operator()(int m, int n, float v) const {
        if (n < FV) {
            float xh = v + bh[n];
            g_xh[m*FV + n] = xh;
            int idx = (m*TV + t)*FV + n;
            float mt = mask[idx];
            float xr = mt * x[idx] + (1.f - mt) * xh;
            ASWZ_W[AOFF_G2 + aidx(m, n, 32)] = f2tf(xr);
        } else {
            g_gh[m*3*HV + (n - FV)] = v + bhh[n - FV];
        }
        return 0.f;
    }
    __device__ void store_partial(int, float) const {}
};
struct EP_G2 {
    const float* bfr; const float* x; const float* mask;
    float* rec; float* ximp; int t;
    static constexpr bool RED = true;
    __device__ float operator()(int m, int n, float v) const {
        float xu = v + bfr[n];
        float xh = g_xh[m*FV + n];
        float be = g_beta[(size_t)t*BV*FV + m*FV + n];
        float xc = be * xu + (1.f - be) * xh;
        int idx = (m*TV + t)*FV + n;
        float mt = mask[idx], xt = x[idx];
        rec[idx]  = xc;
        float xi = mt * xt + (1.f - mt) * xc;
        ximp[idx] = xi;
        ASWZ_W[AOFF_G3 + t*AG3_STRIDE + aidx(m, n, 64)] = f2tf(xi);
        return fabsf(xc - xt) * mt;
    }
    __device__ void store_partial(int lin, float v) const {
        g_lossPart[t*NB2 + lin] = v;
    }
};
struct EP_G3 {
    const float* bih;
    static constexpr bool RED = false;
    __device__ float operator()(int m, int n, float v) const {
        g_gi[m*3*HV + n] = v + bih[n];
        return 0.f;
    }
    __device__ void store_partial(int, float) const {}
};

// ---------------- elementwise kernels ----------------

__global__ void msum_k(const float* __restrict__ mask) {
    int t = blockIdx.x;
    float s = 0.f;
    for (int i = threadIdx.x; i < BV*FV; i += 256) {
        int b = i >> 8, f = i & 255;
        s += mask[(b*TV + t)*FV + f];
    }
    __shared__ float red[256];
    red[threadIdx.x] = s;
    __syncthreads();
    for (int st = 128; st > 0; st >>= 1) {
        if (threadIdx.x < st) red[threadIdx.x] += red[threadIdx.x + st];
        __syncthreads();
    }
    if (threadIdx.x == 0) g_msum[t] = red[0];
}

// GRU update; also produces next step's swizzled A (h_new * gammaH[t+1])
__global__ void gru_k(int t, float* __restrict__ hfin) {
    int idx = blockIdx.x * blockDim.x + threadIdx.x;  // B*H
    int b = idx >> 10, j = idx & 1023;
    float hd = g_h[idx] * g_gammaH[(size_t)t*BV*HV + idx];
    int base = b*3*HV + j;
    float r = 1.f / (1.f + expf(-(g_gi[base]        + g_gh[base])));
    float z = 1.f / (1.f + expf(-(g_gi[base + HV]   + g_gh[base + HV])));
    float n = tanhf(g_gi[base + 2*HV] + r * g_gh[base + 2*HV]);
    float hn = (1.f - z) * n + z * hd;
    g_h[idx] = hn;
    if (t + 1 < TV)
        ASWZ_W[AOFF_G1 + aidx(b, j, 128)] =
            f2tf(hn * g_gammaH[(size_t)(t+1)*BV*HV + idx]);
    if (hfin) hfin[idx] = hn;
}

__global__ void final_k(float* __restrict__ out) {
    __shared__ float s[TV];
    int t = threadIdx.x;  // 64 threads
    float acc = 0.f;
    for (int i = 0; i < NB2; i++) acc += g_lossPart[t*NB2 + i];
    s[t] = acc / (g_msum[t] + 1e-12f);
    __syncthreads();
    if (t == 0) {
        float L = 0.f;
        for (int i = 0; i < TV; i++) L += s[i];
        out[OFF_LOSS]     = L;
        out[OFF_LOSS + 1] = 0.f;  // kl_loss
    }
}

// ---------------- launch ----------------

extern "C" void kernel_launch(void* const* d_in, const int* in_sizes, int n_in,
                              void* d_out, int out_size) {
    const float* x      = (const float*)d_in[0];
    const float* mask   = (const float*)d_in[1];
    const float* deltas = (const float*)d_in[2];
    const float* h0     = (const float*)d_in[3];
    const float* Wdh    = (const float*)d_in[4];
    const float* bdh    = (const float*)d_in[5];
    const float* Wdx    = (const float*)d_in[6];
    const float* bdx    = (const float*)d_in[7];
    const float* Wh     = (const float*)d_in[8];
    const float* bh     = (const float*)d_in[9];
    const float* Wfr    = (const float*)d_in[10];
    const float* bfr    = (const float*)d_in[11];
    const float* Wwc    = (const float*)d_in[12];
    const float* bwc    = (const float*)d_in[13];
    const float* Wih    = (const float*)d_in[14];
    const float* bih    = (const float*)d_in[15];
    const float* Whh    = (const float*)d_in[16];
    const float* bhh    = (const float*)d_in[17];

    float* out      = (float*)d_out;
    float* ximp_out = out;
    float* rec_out  = out + OFF_REC;
    float* hfin     = out + OFF_HFIN;

    msum_k<<<TV, 256>>>(mask);

    // Pre-swizzle weights (B operands)
    swz_k<<<(3328*1024)/256, 256>>>(BOFF_G1, 3328, 1024, BL_G1{Wh, Whh});
    swz_k<<<(3072*512 )/256, 256>>>(BOFF_G3, 3072, 512,  BL_G3{Wih});
    swz_k<<<(256*256  )/256, 256>>>(BOFF_G2, 256,  256,  BL_G2{Wfr});
    swz_k<<<(1024*256 )/256, 256>>>(BOFF_P1, 1024, 256,  BL_P1{Wdh});
    swz_k<<<(256*512  )/256, 256>>>(BOFF_P2, 256,  512,  BL_P2{Wwc});

    // Pre-swizzle A operands for P1/P2 and G3 mask half
    swzA_P1_k<<<(32768*256)/256, 256>>>(deltas);
    swzA_P2_k<<<(32768*512)/256, 256>>>(deltas, mask, Wdx, bdx);
    swzA_G3m_k<<<(TV*BV*FV)/256, 256>>>(mask);

    // P1: gammaH, M=32768, N=1024, K=256
    tgemm4_k<64,128,32,32><<<dim3(1024/128, 32768/64), 256>>>(
        FV, AOFF_P1, BOFF_P1, EP_P1{bdh});

    // h init (needs gammaH[0])
    hAinit_k<<<(BV*HV)/256, 256>>>(h0);

    // P2: beta, M=32768, N=256, K=512
    tgemm4_k<64,128,32,32><<<dim3(256/128, 32768/64), 256>>>(
        2*FV, AOFF_P2, BOFF_P2, EP_P2{bwc});

    for (int t = 0; t < TV; t++) {
        // G1: [x_h | gh], M=512, N=3328, K=1024 -> 208 blocks
        tgemm4_k<64,128,32,32><<<dim3(3328/128, 512/64), 256>>>(
            HV, AOFF_G1, BOFF_G1, EP_G1{bh, bhh, x, mask, t});

        // G2: xu + combine/imputation/loss, M=512, N=256, K=256 -> 32 blocks
        tgemm4_k<64,64,32,16><<<dim3(256/64, 512/64), 256>>>(
            FV, AOFF_G2, BOFF_G2, EP_G2{bfr, x, mask, rec_out, ximp_out, t});

        // G3: gi, M=512, N=3072, K=512 -> 192 blocks
        tgemm4_k<64,128,32,32><<<dim3(3072/128, 512/64), 256>>>(
            2*FV, AOFF_G3 + t*AG3_STRIDE, BOFF_G3, EP_G3{bih});

        // GRU elementwise update (+ next step's swizzled A)
        gru_k<<<(BV*HV)/256, 256>>>(t, (t == TV-1) ? hfin : nullptr);
    }

    final_k<<<1, TV>>>(out);
}

// round 12
// speedup vs baseline: 1.1257x; 1.0734x over previous
#include <cuda_runtime.h>
#include <math.h>
#include <stdint.h>

// Problem constants
#define BV 512
#define TV 64
#define FV 256
#define HV 1024

// Output layout: x_imp [B,T,F] | reconstruction [B,T,F] | h_fin [B,H] | x_loss | kl_loss
#define OFF_REC   (BV*TV*FV)
#define OFF_HFIN  (2*BV*TV*FV)
#define OFF_LOSS  (2*BV*TV*FV + BV*HV)

#define NB2 32   // loss partial tiles per step

// ---------------- scratch ----------------
__device__ float g_h[BV*HV];
__device__ float g_xh[BV*FV];
__device__ float g_gh[BV*3*HV];
__device__ float g_gi[BV*3*HV];
__device__ float g_gammaH[(size_t)TV*BV*HV];
__device__ float g_beta[(size_t)TV*BV*FV];
__device__ float g_msum[TV];
__device__ float g_lossPart[TV*NB2];

// ---- pre-swizzled tf32 B (weights), uint2 fragment granularity ----
#define SZ2(N,K) ((N)*(K)/2)
#define BOFF_G1 0
#define BOFF_G3 (BOFF_G1 + SZ2(3328,1024))
#define BOFF_G2 (BOFF_G3 + SZ2(3072,512))
#define BOFF_P1 (BOFF_G2 + SZ2(256,256))
#define BOFF_P2 (BOFF_P1 + SZ2(1024,256))
#define BSWZ_TOTAL (BOFF_P2 + SZ2(256,512))
__device__ uint2 g_Bswz[BSWZ_TOTAL];

// ---- pre-swizzled tf32 A (activations), uint32 words, 16B-aligned ----
#define AOFF_G1 0                                   // 512x1024
#define AOFF_G2 (AOFF_G1 + BV*HV)                   // 512x256
#define AOFF_G3 (AOFF_G2 + BV*FV)                   // 64 slices of 512x512
#define AG3_STRIDE (BV*2*FV)
#define AOFF_P1 (AOFF_G3 + TV*AG3_STRIDE)           // 32768x256
#define AOFF_P2 (AOFF_P1 + TV*BV*FV)                // 32768x512
#define ASWZ_TOTAL (AOFF_P2 + TV*BV*2*FV)
__device__ uint4 g_Aswz4[ASWZ_TOTAL/4];
#define ASWZ_W ((uint32_t*)g_Aswz4)

__device__ __forceinline__ uint32_t f2tf(float f) {
    uint32_t r;
    asm("cvt.rna.tf32.f32 %0, %1;" : "=r"(r) : "f"(f));
    return r;
}

// word index of element (m,k) in fragment-native A layout (KTT = K/8)
__device__ __forceinline__ int aidx(int m, int k, int KTT) {
    int r = m & 15, c = k & 7;
    return (((m >> 4)*KTT + (k >> 3))*32 + (r & 7)*4 + (c & 3))*4
           + (r >> 3) + (((k >> 2) & 1) << 1);
}

// ---------------- weight pre-swizzle: B(n,k) -> fragment-native tf32 ----------------
template<class BL>
__global__ void swz_k(int boff, int N, int K, BL bl) {
    int idx = blockIdx.x * 256 + threadIdx.x;
    if (idx >= N*K) return;
    int n = idx / K, k = idx % K;
    int KTT = K >> 3;
    uint32_t* d = (uint32_t*)(g_Bswz + boff);
    int off = (((n>>3)*KTT + (k>>3))*32 + ((n&7)*4 + (k&3)))*2 + ((k>>2)&1);
    d[off] = f2tf(bl(n, k));
}

// ------------- tf32 GEMM: pre-swizzled A via smem, B via tail-prefetched LDG -------------
// C[m,n] = sum_k A(m,k)*B(n,k). 256 threads = 8 warps. BK = 32 (KT = 4 k8-tiles).
// B fragments for iteration i+1 are loaded at the BOTTOM of iteration i (in-place,
// zero extra registers) so their L2 latency hides behind a full compute iteration.
template<int BM,int BN,int WM,int WN,class EP>
__global__ __launch_bounds__(256, 2)
void tgemm4_k(int K, int aoff, int boff, EP ep) {
    constexpr int WARPS_M = BM/WM, WARPS_N = BN/WN;
    static_assert(WARPS_M*WARPS_N == 8, "need 8 warps");
    constexpr int MI = WM/16, NI = WN/8;
    constexpr int KT = 4;                         // k8-tiles per BK=32 tile
    constexpr int TILE4 = (BM/16)*KT*32;          // uint4 per A tile
    constexpr int CP = TILE4/256;                 // uint4 per thread per copy

    __shared__ uint4 As[2][TILE4];
    __shared__ float red[256];

    const int KTT = K >> 3;
    const int tid = threadIdx.x, lane = tid & 31, wid = tid >> 5;
    const int wm = (wid % WARPS_M)*WM, wn = (wid / WARPS_M)*WN;
    const int gid = lane >> 2, tig = lane & 3;
    const int bm = blockIdx.y*BM, bn = blockIdx.x*BN;
    const int mtBase = bm >> 4;
    const int ntBase = (bn + wn) >> 3;
    const int wmt = wm >> 4;

    const uint4* __restrict__ Ag = (const uint4*)(ASWZ_W + aoff);
    const uint2* __restrict__ Bg = g_Bswz + boff;

    float acc[MI][NI][4];
    #pragma unroll
    for (int mi = 0; mi < MI; mi++)
        #pragma unroll
        for (int ni = 0; ni < NI; ni++)
            #pragma unroll
            for (int c = 0; c < 4; c++) acc[mi][ni][c] = 0.f;

    uint4 ar[CP];
    auto ldA = [&](int kt0) {
        #pragma unroll
        for (int i = 0; i < CP; i++) {
            int e = tid + i*256;
            int mtl = e / (KT*32), rem = e % (KT*32);
            ar[i] = Ag[((mtBase + mtl)*KTT + kt0 + rem/32)*32 + (rem & 31)];
        }
    };
    auto stA = [&](int buf) {
        #pragma unroll
        for (int i = 0; i < CP; i++) As[buf][tid + i*256] = ar[i];
    };

    uint2 bf[NI][KT];
    auto ldB = [&](int kt0) {
        #pragma unroll
        for (int ni = 0; ni < NI; ni++)
            #pragma unroll
            for (int kk = 0; kk < KT; kk++)
                bf[ni][kk] = Bg[((ntBase + ni)*KTT + kt0 + kk)*32 + lane];
    };

    // prologue: tile 0 operands
    ldA(0); stA(0);
    ldB(0);
    __syncthreads();

    int cur = 0;
    for (int kt0 = 0; kt0 < KTT; kt0 += KT) {
        const bool more = (kt0 + KT) < KTT;
        if (more) ldA(kt0 + KT);   // A prefetch (regs), hidden by kk loop

        #pragma unroll
        for (int kk = 0; kk < KT; kk++) {
            uint4 av[MI];
            #pragma unroll
            for (int mi = 0; mi < MI; mi++)
                av[mi] = As[cur][((wmt + mi)*KT + kk)*32 + lane];
            #pragma unroll
            for (int mi = 0; mi < MI; mi++)
                #pragma unroll
                for (int ni = 0; ni < NI; ni++)
                    asm volatile(
                        "mma.sync.aligned.m16n8k8.row.col.f32.tf32.tf32.f32 "
                        "{%0,%1,%2,%3}, {%4,%5,%6,%7}, {%8,%9}, {%0,%1,%2,%3};"
                        : "+f"(acc[mi][ni][0]), "+f"(acc[mi][ni][1]),
                          "+f"(acc[mi][ni][2]), "+f"(acc[mi][ni][3])
                        : "r"(av[mi].x), "r"(av[mi].y), "r"(av[mi].z), "r"(av[mi].w),
                          "r"(bf[ni][kk].x), "r"(bf[ni][kk].y));
        }
        if (more) {
            ldB(kt0 + KT);          // tail-prefetch B for next iter (in place, 0 extra regs)
            stA(cur ^ 1);
        }
        __syncthreads();
        cur ^= 1;
    }

    float rsum = 0.f;
    #pragma unroll
    for (int mi = 0; mi < MI; mi++) {
        #pragma unroll
        for (int ni = 0; ni < NI; ni++) {
            int gm0 = bm + wm + mi*16 + gid;
            int gn0 = bn + wn + ni*8 + tig*2;
            rsum += ep(gm0,     gn0,     acc[mi][ni][0]);
            rsum += ep(gm0,     gn0 + 1, acc[mi][ni][1]);
            rsum += ep(gm0 + 8, gn0,     acc[mi][ni][2]);
            rsum += ep(gm0 + 8, gn0 + 1, acc[mi][ni][3]);
        }
    }

    if constexpr (EP::RED) {
        red[tid] = rsum;
        __syncthreads();
        for (int s = 128; s > 0; s >>= 1) {
            if (tid < s) red[tid] += red[tid + s];
            __syncthreads();
        }
        if (tid == 0) {
            int lin = blockIdx.y * gridDim.x + blockIdx.x;
            ep.store_partial(lin, red[0]);
        }
    }
}

// ---------------- B-side scalar loaders (used only by swz_k) ----------------

struct BL_P1 {
    const float* Wdh;
    __device__ float operator()(int n, int k) const { return Wdh[n*FV + k]; }
};
struct BL_P2 {
    const float* Wwc;
    __device__ float operator()(int n, int k) const { return Wwc[n*(2*FV) + k]; }
};
struct BL_G1 {
    const float* Wh; const float* Whh;
    __device__ float operator()(int n, int k) const {
        return (n < FV) ? Wh[n*HV + k] : Whh[(n - FV)*HV + k];
    }
};
struct BL_G2 {
    const float* Wfr;
    __device__ float operator()(int n, int k) const {
        return (n == k) ? 0.f : Wfr[n*FV + k];
    }
};
struct BL_G3 {
    const float* Wih;
    __device__ float operator()(int n, int k) const { return Wih[n*(2*FV) + k]; }
};

// ---------------- A-side pre-swizzle kernels ----------------

__global__ void swzA_P1_k(const float* __restrict__ deltas) {
    int idx = blockIdx.x * 256 + threadIdx.x;   // 32768*256
    int m = idx >> 8, k = idx & 255;
    int t = m >> 9, b = m & 511;
    ASWZ_W[AOFF_P1 + aidx(m, k, 32)] = f2tf(deltas[(b*TV + t)*FV + k]);
}

__global__ void swzA_P2_k(const float* __restrict__ deltas, const float* __restrict__ mask,
                          const float* __restrict__ Wdx, const float* __restrict__ bdx) {
    int idx = blockIdx.x * 256 + threadIdx.x;   // 32768*512
    int m = idx >> 9, k = idx & 511;
    int t = m >> 9, b = m & 511;
    float v;
    if (k < FV) {
        float d = deltas[(b*TV + t)*FV + k];
        v = expf(-fmaxf(d * Wdx[k*FV + k] + bdx[k], 0.f));
    } else {
        v = mask[(b*TV + t)*FV + (k - FV)];
    }
    ASWZ_W[AOFF_P2 + aidx(m, k, 64)] = f2tf(v);
}

__global__ void swzA_G3m_k(const float* __restrict__ mask) {
    int idx = blockIdx.x * 256 + threadIdx.x;   // 64*512*256
    int t = idx >> 17, b = (idx >> 8) & 511, f = idx & 255;
    ASWZ_W[AOFF_G3 + t*AG3_STRIDE + aidx(b, FV + f, 64)] =
        f2tf(mask[(b*TV + t)*FV + f]);
}

// h init: plain h0 + swizzled h0*gammaH[0] (run after P1 GEMM)
__global__ void hAinit_k(const float* __restrict__ h0) {
    int idx = blockIdx.x * 256 + threadIdx.x;   // B*H
    int b = idx >> 10, j = idx & 1023;
    float h = h0[idx];
    g_h[idx] = h;
    ASWZ_W[AOFF_G1 + aidx(b, j, 128)] = f2tf(h * g_gammaH[idx]);
}

// ---------------- epilogues ----------------

struct EP_P1 {
    const float* bdh;
    static constexpr bool RED = false;
    __device__ float operator()(int m, int n, float v) const {
        g_gammaH[(size_t)m*HV + n] = expf(-fmaxf(v + bdh[n], 0.f));
        return 0.f;
    }
    __device__ void store_partial(int, float) const {}
};
struct EP_P2 {
    const float* bwc;
    static constexpr bool RED = false;
    __device__ float operator()(int m, int n, float v) const {
        g_beta[(size_t)m*FV + n] = v + bwc[n];
        return 0.f;
    }
    __device__ void store_partial(int, float) const {}
};
struct EP_G1 {
    const float* bh; const float* bhh; const float* x; const float* mask; int t;
    static constexpr bool RED = false;
    __device__ float operator()(int m, int n, float v) const {
        if (n < FV) {
            float xh = v + bh[n];
            g_xh[m*FV + n] = xh;
            int idx = (m*TV + t)*FV + n;
            float mt = mask[idx];
            float xr = mt * x[idx] + (1.f - mt) * xh;
            ASWZ_W[AOFF_G2 + aidx(m, n, 32)] = f2tf(xr);
        } else {
            g_gh[m*3*HV + (n - FV)] = v + bhh[n - FV];
        }
        return 0.f;
    }
    __device__ void store_partial(int, float) const {}
};
struct EP_G2 {
    const float* bfr; const float* x; const float* mask;
    float* rec; float* ximp; int t;
    static constexpr bool RED = true;
    __device__ float operator()(int m, int n, float v) const {
        float xu = v + bfr[n];
        float xh = g_xh[m*FV + n];
        float be = g_beta[(size_t)t*BV*FV + m*FV + n];
        float xc = be * xu + (1.f - be) * xh;
        int idx = (m*TV + t)*FV + n;
        float mt = mask[idx], xt = x[idx];
        rec[idx]  = xc;
        float xi = mt * xt + (1.f - mt) * xc;
        ximp[idx] = xi;
        ASWZ_W[AOFF_G3 + t*AG3_STRIDE + aidx(m, n, 64)] = f2tf(xi);
        return fabsf(xc - xt) * mt;
    }
    __device__ void store_partial(int lin, float v) const {
        g_lossPart[t*NB2 + lin] = v;
    }
};
struct EP_G3 {
    const float* bih;
    static constexpr bool RED = false;
    __device__ float operator()(int m, int n, float v) const {
        g_gi[m*3*HV + n] = v + bih[n];
        return 0.f;
    }
    __device__ void store_partial(int, float) const {}
};

// ---------------- elementwise kernels ----------------

__global__ void msum_k(const float* __restrict__ mask) {
    int t = blockIdx.x;
    float s = 0.f;
    for (int i = threadIdx.x; i < BV*FV; i += 256) {
        int b = i >> 8, f = i & 255;
        s += mask[(b*TV + t)*FV + f];
    }
    __shared__ float red[256];
    red[threadIdx.x] = s;
    __syncthreads();
    for (int st = 128; st > 0; st >>= 1) {
        if (threadIdx.x < st) red[threadIdx.x] += red[threadIdx.x + st];
        __syncthreads();
    }
    if (threadIdx.x == 0) g_msum[t] = red[0];
}

// GRU update; also produces next step's swizzled A (h_new * gammaH[t+1])
__global__ void gru_k(int t, float* __restrict__ hfin) {
    int idx = blockIdx.x * blockDim.x + threadIdx.x;  // B*H
    int b = idx >> 10, j = idx & 1023;
    float hd = g_h[idx] * g_gammaH[(size_t)t*BV*HV + idx];
    int base = b*3*HV + j;
    float r = 1.f / (1.f + expf(-(g_gi[base]        + g_gh[base])));
    float z = 1.f / (1.f + expf(-(g_gi[base + HV]   + g_gh[base + HV])));
    float n = tanhf(g_gi[base + 2*HV] + r * g_gh[base + 2*HV]);
    float hn = (1.f - z) * n + z * hd;
    g_h[idx] = hn;
    if (t + 1 < TV)
        ASWZ_W[AOFF_G1 + aidx(b, j, 128)] =
            f2tf(hn * g_gammaH[(size_t)(t+1)*BV*HV + idx]);
    if (hfin) hfin[idx] = hn;
}

__global__ void final_k(float* __restrict__ out) {
    __shared__ float s[TV];
    int t = threadIdx.x;  // 64 threads
    float acc = 0.f;
    for (int i = 0; i < NB2; i++) acc += g_lossPart[t*NB2 + i];
    s[t] = acc / (g_msum[t] + 1e-12f);
    __syncthreads();
    if (t == 0) {
        float L = 0.f;
        for (int i = 0; i < TV; i++) L += s[i];
        out[OFF_LOSS]     = L;
        out[OFF_LOSS + 1] = 0.f;  // kl_loss
    }
}

// ---------------- launch ----------------

extern "C" void kernel_launch(void* const* d_in, const int* in_sizes, int n_in,
                              void* d_out, int out_size) {
    const float* x      = (const float*)d_in[0];
    const float* mask   = (const float*)d_in[1];
    const float* deltas = (const float*)d_in[2];
    const float* h0     = (const float*)d_in[3];
    const float* Wdh    = (const float*)d_in[4];
    const float* bdh    = (const float*)d_in[5];
    const float* Wdx    = (const float*)d_in[6];
    const float* bdx    = (const float*)d_in[7];
    const float* Wh     = (const float*)d_in[8];
    const float* bh     = (const float*)d_in[9];
    const float* Wfr    = (const float*)d_in[10];
    const float* bfr    = (const float*)d_in[11];
    const float* Wwc    = (const float*)d_in[12];
    const float* bwc    = (const float*)d_in[13];
    const float* Wih    = (const float*)d_in[14];
    const float* bih    = (const float*)d_in[15];
    const float* Whh    = (const float*)d_in[16];
    const float* bhh    = (const float*)d_in[17];

    float* out      = (float*)d_out;
    float* ximp_out = out;
    float* rec_out  = out + OFF_REC;
    float* hfin     = out + OFF_HFIN;

    msum_k<<<TV, 256>>>(mask);

    // Pre-swizzle weights (B operands)
    swz_k<<<(3328*1024)/256, 256>>>(BOFF_G1, 3328, 1024, BL_G1{Wh, Whh});
    swz_k<<<(3072*512 )/256, 256>>>(BOFF_G3, 3072, 512,  BL_G3{Wih});
    swz_k<<<(256*256  )/256, 256>>>(BOFF_G2, 256,  256,  BL_G2{Wfr});
    swz_k<<<(1024*256 )/256, 256>>>(BOFF_P1, 1024, 256,  BL_P1{Wdh});
    swz_k<<<(256*512  )/256, 256>>>(BOFF_P2, 256,  512,  BL_P2{Wwc});

    // Pre-swizzle A operands for P1/P2 and G3 mask half
    swzA_P1_k<<<(32768*256)/256, 256>>>(deltas);
    swzA_P2_k<<<(32768*512)/256, 256>>>(deltas, mask, Wdx, bdx);
    swzA_G3m_k<<<(TV*BV*FV)/256, 256>>>(mask);

    // P1: gammaH, M=32768, N=1024, K=256
    tgemm4_k<64,128,32,32><<<dim3(1024/128, 32768/64), 256>>>(
        FV, AOFF_P1, BOFF_P1, EP_P1{bdh});

    // h init (needs gammaH[0])
    hAinit_k<<<(BV*HV)/256, 256>>>(h0);

    // P2: beta, M=32768, N=256, K=512
    tgemm4_k<64,128,32,32><<<dim3(256/128, 32768/64), 256>>>(
        2*FV, AOFF_P2, BOFF_P2, EP_P2{bwc});

    for (int t = 0; t < TV; t++) {
        // G1: [x_h | gh], M=512, N=3328, K=1024 -> 208 blocks
        tgemm4_k<64,128,32,32><<<dim3(3328/128, 512/64), 256>>>(
            HV, AOFF_G1, BOFF_G1, EP_G1{bh, bhh, x, mask, t});

        // G2: xu + combine/imputation/loss, M=512, N=256, K=256 -> 32 blocks
        tgemm4_k<64,64,32,16><<<dim3(256/64, 512/64), 256>>>(
            FV, AOFF_G2, BOFF_G2, EP_G2{bfr, x, mask, rec_out, ximp_out, t});

        // G3: gi, M=512, N=3072, K=512 -> 192 blocks
        tgemm4_k<64,128,32,32><<<dim3(3072/128, 512/64), 256>>>(
            2*FV, AOFF_G3 + t*AG3_STRIDE, BOFF_G3, EP_G3{bih});

        // GRU elementwise update (+ next step's swizzled A)
        gru_k<<<(BV*HV)/256, 256>>>(t, (t == TV-1) ? hfin : nullptr);
    }

    final_k<<<1, TV>>>(out);
}

// round 13
// speedup vs baseline: 1.4403x; 1.2795x over previous
#include <cuda_runtime.h>
#include <cuda_fp16.h>
#include <math.h>
#include <stdint.h>

// Problem constants
#define BV 512
#define TV 64
#define FV 256
#define HV 1024

// Output layout: x_imp [B,T,F] | reconstruction [B,T,F] | h_fin [B,H] | x_loss | kl_loss
#define OFF_REC   (BV*TV*FV)
#define OFF_HFIN  (2*BV*TV*FV)
#define OFF_LOSS  (2*BV*TV*FV + BV*HV)

#define NB2 32   // loss partial tiles per step

// ---------------- scratch ----------------
__device__ float g_h[BV*HV];
__device__ float g_xh[BV*FV];
__device__ float g_gh[BV*3*HV];
__device__ float g_gi[BV*3*HV];
__device__ float g_gammaH[(size_t)TV*BV*HV];
__device__ float g_beta[(size_t)TV*BV*FV];
__device__ float g_msum[TV];
__device__ float g_lossPart[TV*NB2];

// ---- pre-swizzled fp16 B (weights); uint2 = one (n8,k16) lane fragment ----
#define SZB(N,K) ((N)*(K)/4)
#define BOFF_G1 0
#define BOFF_G3 (BOFF_G1 + SZB(3328,1024))
#define BOFF_G2 (BOFF_G3 + SZB(3072,512))
#define BOFF_P1 (BOFF_G2 + SZB(256,256))
#define BOFF_P2 (BOFF_P1 + SZB(1024,256))
#define BSWZ_TOTAL (BOFF_P2 + SZB(256,512))
__device__ uint2 g_Bswz[BSWZ_TOTAL];

// ---- pre-swizzled fp16 A (activations); offsets in ELEMENT (halfword) units ----
#define AOFF_G1 0                                   // 512x1024
#define AOFF_G2 (AOFF_G1 + BV*HV)                   // 512x256
#define AOFF_G3 (AOFF_G2 + BV*FV)                   // 64 slices of 512x512
#define AG3_STRIDE (BV*2*FV)
#define AOFF_P1 (AOFF_G3 + TV*AG3_STRIDE)           // 32768x256
#define AOFF_P2 (AOFF_P1 + TV*BV*FV)                // 32768x512
#define ASWZ_TOTAL (AOFF_P2 + TV*BV*2*FV)
__device__ uint4 g_Aswz4[ASWZ_TOTAL/8];
#define ASWZ_H ((uint16_t*)g_Aswz4)

__device__ __forceinline__ uint16_t f2h(float f) {
    return __half_as_ushort(__float2half_rn(f));
}

// element index of A(m,k) in fp16 m16n8k16 fragment-native layout (KT16 = K/16)
__device__ __forceinline__ int aidx16(int m, int k, int KT16) {
    int r = m & 15, c = k & 15;
    int lane = (r & 7)*4 + ((c & 7) >> 1);
    int reg  = (r >> 3) + ((c >> 3) << 1);
    return ((((m >> 4)*KT16 + (k >> 4))*32 + lane)*4 + reg)*2 + (c & 1);
}
// element index of B(n,k) in fp16 m16n8k16 fragment-native layout
__device__ __forceinline__ int bidx16(int n, int k, int KT16) {
    int c = k & 15;
    int lane = (n & 7)*4 + ((c & 7) >> 1);
    int reg  = (c >> 3) & 1;
    return ((((n >> 3)*KT16 + (k >> 4))*32 + lane)*2 + reg)*2 + (k & 1);
}

// ---------------- weight pre-swizzle: B(n,k) -> fragment-native fp16 ----------------
template<class BL>
__global__ void swz_k(int boff, int N, int K, BL bl) {
    int idx = blockIdx.x * 256 + threadIdx.x;
    if (idx >= N*K) return;
    int n = idx / K, k = idx % K;
    uint16_t* d = (uint16_t*)(g_Bswz + boff);
    d[bidx16(n, k, K >> 4)] = f2h(bl(n, k));
}

// ------------- fp16 m16n8k16 GEMM: pre-swizzled A via smem, B direct LDG -------------
// C[m,n] = sum_k A(m,k)*B(n,k), fp32 accumulate. 256 threads = 8 warps. BK = 32.
template<int BM,int BN,int WM,int WN,class EP>
__global__ __launch_bounds__(256, 2)
void tgemm4_k(int K, int aoff, int boff, EP ep) {
    constexpr int WARPS_M = BM/WM, WARPS_N = BN/WN;
    static_assert(WARPS_M*WARPS_N == 8, "need 8 warps");
    constexpr int MI = WM/16, NI = WN/8;
    constexpr int KT = 2;                         // k16-tiles per BK=32 tile
    constexpr int TILE4 = (BM/16)*KT*32;          // uint4 per A tile (256 for BM=64)
    constexpr int CP = TILE4/256;

    __shared__ uint4 As[2][TILE4];
    __shared__ float red[256];

    const int KT16 = K >> 4;
    const int tid = threadIdx.x, lane = tid & 31, wid = tid >> 5;
    const int wm = (wid % WARPS_M)*WM, wn = (wid / WARPS_M)*WN;
    const int gid = lane >> 2, tig = lane & 3;
    const int bm = blockIdx.y*BM, bn = blockIdx.x*BN;
    const int mtBase = bm >> 4;
    const int ntBase = (bn + wn) >> 3;
    const int wmt = wm >> 4;

    const uint4* __restrict__ Ag = (const uint4*)(ASWZ_H + aoff);
    const uint2* __restrict__ Bg = g_Bswz + boff;

    float acc[MI][NI][4];
    #pragma unroll
    for (int mi = 0; mi < MI; mi++)
        #pragma unroll
        for (int ni = 0; ni < NI; ni++)
            #pragma unroll
            for (int c = 0; c < 4; c++) acc[mi][ni][c] = 0.f;

    uint4 ar[CP];
    auto ldA = [&](int kt0) {
        #pragma unroll
        for (int i = 0; i < CP; i++) {
            int e = tid + i*256;
            int mtl = e / (KT*32), rem = e % (KT*32);
            ar[i] = Ag[((mtBase + mtl)*KT16 + kt0 + rem/32)*32 + (rem & 31)];
        }
    };
    auto stA = [&](int buf) {
        #pragma unroll
        for (int i = 0; i < CP; i++) As[buf][tid + i*256] = ar[i];
    };

    ldA(0); stA(0);
    __syncthreads();

    int cur = 0;
    for (int kt0 = 0; kt0 < KT16; kt0 += KT) {
        const bool more = (kt0 + KT) < KT16;
        // B fragments for this tile: direct LDG.64 from pre-swizzled global
        uint2 bf[NI][KT];
        #pragma unroll
        for (int ni = 0; ni < NI; ni++)
            #pragma unroll
            for (int kk = 0; kk < KT; kk++)
                bf[ni][kk] = Bg[((ntBase + ni)*KT16 + kt0 + kk)*32 + lane];
        if (more) ldA(kt0 + KT);

        #pragma unroll
        for (int kk = 0; kk < KT; kk++) {
            uint4 av[MI];
            #pragma unroll
            for (int mi = 0; mi < MI; mi++)
                av[mi] = As[cur][((wmt + mi)*KT + kk)*32 + lane];
            #pragma unroll
            for (int mi = 0; mi < MI; mi++)
                #pragma unroll
                for (int ni = 0; ni < NI; ni++)
                    asm volatile(
                        "mma.sync.aligned.m16n8k16.row.col.f32.f16.f16.f32 "
                        "{%0,%1,%2,%3}, {%4,%5,%6,%7}, {%8,%9}, {%0,%1,%2,%3};"
                        : "+f"(acc[mi][ni][0]), "+f"(acc[mi][ni][1]),
                          "+f"(acc[mi][ni][2]), "+f"(acc[mi][ni][3])
                        : "r"(av[mi].x), "r"(av[mi].y), "r"(av[mi].z), "r"(av[mi].w),
                          "r"(bf[ni][kk].x), "r"(bf[ni][kk].y));
        }
        if (more) stA(cur ^ 1);
        __syncthreads();
        cur ^= 1;
    }

    float rsum = 0.f;
    #pragma unroll
    for (int mi = 0; mi < MI; mi++) {
        #pragma unroll
        for (int ni = 0; ni < NI; ni++) {
            int gm0 = bm + wm + mi*16 + gid;
            int gn0 = bn + wn + ni*8 + tig*2;
            rsum += ep(gm0,     gn0,     acc[mi][ni][0]);
            rsum += ep(gm0,     gn0 + 1, acc[mi][ni][1]);
            rsum += ep(gm0 + 8, gn0,     acc[mi][ni][2]);
            rsum += ep(gm0 + 8, gn0 + 1, acc[mi][ni][3]);
        }
    }

    if constexpr (EP::RED) {
        red[tid] = rsum;
        __syncthreads();
        for (int s = 128; s > 0; s >>= 1) {
            if (tid < s) red[tid] += red[tid + s];
            __syncthreads();
        }
        if (tid == 0) {
            int lin = blockIdx.y * gridDim.x + blockIdx.x;
            ep.store_partial(lin, red[0]);
        }
    }
}

// ---------------- B-side scalar loaders (used only by swz_k) ----------------

struct BL_P1 {
    const float* Wdh;
    __device__ float operator()(int n, int k) const { return Wdh[n*FV + k]; }
};
struct BL_P2 {
    const float* Wwc;
    __device__ float operator()(int n, int k) const { return Wwc[n*(2*FV) + k]; }
};
struct BL_G1 {
    const float* Wh; const float* Whh;
    __device__ float operator()(int n, int k) const {
        return (n < FV) ? Wh[n*HV + k] : Whh[(n - FV)*HV + k];
    }
};
struct BL_G2 {
    const float* Wfr;
    __device__ float operator()(int n, int k) const {
        return (n == k) ? 0.f : Wfr[n*FV + k];
    }
};
struct BL_G3 {
    const float* Wih;
    __device__ float operator()(int n, int k) const { return Wih[n*(2*FV) + k]; }
};

// ---------------- A-side pre-swizzle kernels ----------------

__global__ void swzA_P1_k(const float* __restrict__ deltas) {
    int idx = blockIdx.x * 256 + threadIdx.x;   // 32768*256
    int m = idx >> 8, k = idx & 255;
    int t = m >> 9, b = m & 511;
    ASWZ_H[AOFF_P1 + aidx16(m, k, 16)] = f2h(deltas[(b*TV + t)*FV + k]);
}

__global__ void swzA_P2_k(const float* __restrict__ deltas, const float* __restrict__ mask,
                          const float* __restrict__ Wdx, const float* __restrict__ bdx) {
    int idx = blockIdx.x * 256 + threadIdx.x;   // 32768*512
    int m = idx >> 9, k = idx & 511;
    int t = m >> 9, b = m & 511;
    float v;
    if (k < FV) {
        float d = deltas[(b*TV + t)*FV + k];
        v = expf(-fmaxf(d * Wdx[k*FV + k] + bdx[k], 0.f));
    } else {
        v = mask[(b*TV + t)*FV + (k - FV)];
    }
    ASWZ_H[AOFF_P2 + aidx16(m, k, 32)] = f2h(v);
}

__global__ void swzA_G3m_k(const float* __restrict__ mask) {
    int idx = blockIdx.x * 256 + threadIdx.x;   // 64*512*256
    int t = idx >> 17, b = (idx >> 8) & 511, f = idx & 255;
    ASWZ_H[AOFF_G3 + t*AG3_STRIDE + aidx16(b, FV + f, 32)] =
        f2h(mask[(b*TV + t)*FV + f]);
}

// h init: plain h0 + swizzled fp16 h0*gammaH[0] (run after P1 GEMM)
__global__ void hAinit_k(const float* __restrict__ h0) {
    int idx = blockIdx.x * 256 + threadIdx.x;   // B*H
    int b = idx >> 10, j = idx & 1023;
    float h = h0[idx];
    g_h[idx] = h;
    ASWZ_H[AOFF_G1 + aidx16(b, j, 64)] = f2h(h * g_gammaH[idx]);
}

// ---------------- epilogues ----------------

struct EP_P1 {
    const float* bdh;
    static constexpr bool RED = false;
    __device__ float operator()(int m, int n, float v) const {
        g_gammaH[(size_t)m*HV + n] = expf(-fmaxf(v + bdh[n], 0.f));
        return 0.f;
    }
    __device__ void store_partial(int, float) const {}
};
struct EP_P2 {
    const float* bwc;
    static constexpr bool RED = false;
    __device__ float operator()(int m, int n, float v) const {
        g_beta[(size_t)m*FV + n] = v + bwc[n];
        return 0.f;
    }
    __device__ void store_partial(int, float) const {}
};
struct EP_G1 {
    const float* bh; const float* bhh; const float* x; const float* mask; int t;
    static constexpr bool RED = false;
    __device__ float operator()(int m, int n, float v) const {
        if (n < FV) {
            float xh = v + bh[n];
            g_xh[m*FV + n] = xh;
            int idx = (m*TV + t)*FV + n;
            float mt = mask[idx];
            float xr = mt * x[idx] + (1.f - mt) * xh;
            ASWZ_H[AOFF_G2 + aidx16(m, n, 16)] = f2h(xr);
        } else {
            g_gh[m*3*HV + (n - FV)] = v + bhh[n - FV];
        }
        return 0.f;
    }
    __device__ void store_partial(int, float) const {}
};
struct EP_G2 {
    const float* bfr; const float* x; const float* mask;
    float* rec; float* ximp; int t;
    static constexpr bool RED = true;
    __device__ float operator()(int m, int n, float v) const {
        float xu = v + bfr[n];
        float xh = g_xh[m*FV + n];
        float be = g_beta[(size_t)t*BV*FV + m*FV + n];
        float xc = be * xu + (1.f - be) * xh;
        int idx = (m*TV + t)*FV + n;
        float mt = mask[idx], xt = x[idx];
        rec[idx]  = xc;
        float xi = mt * xt + (1.f - mt) * xc;
        ximp[idx] = xi;
        ASWZ_H[AOFF_G3 + t*AG3_STRIDE + aidx16(m, n, 32)] = f2h(xi);
        return fabsf(xc - xt) * mt;
    }
    __device__ void store_partial(int lin, float v) const {
        g_lossPart[t*NB2 + lin] = v;
    }
};
struct EP_G3 {
    const float* bih;
    static constexpr bool RED = false;
    __device__ float operator()(int m, int n, float v) const {
        g_gi[m*3*HV + n] = v + bih[n];
        return 0.f;
    }
    __device__ void store_partial(int, float) const {}
};

// ---------------- elementwise kernels ----------------

__global__ void msum_k(const float* __restrict__ mask) {
    int t = blockIdx.x;
    float s = 0.f;
    for (int i = threadIdx.x; i < BV*FV; i += 256) {
        int b = i >> 8, f = i & 255;
        s += mask[(b*TV + t)*FV + f];
    }
    __shared__ float red[256];
    red[threadIdx.x] = s;
    __syncthreads();
    for (int st = 128; st > 0; st >>= 1) {
        if (threadIdx.x < st) red[threadIdx.x] += red[threadIdx.x + st];
        __syncthreads();
    }
    if (threadIdx.x == 0) g_msum[t] = red[0];
}

// GRU update; also produces next step's swizzled fp16 A (h_new * gammaH[t+1])
__global__ void gru_k(int t, float* __restrict__ hfin) {
    int idx = blockIdx.x * blockDim.x + threadIdx.x;  // B*H
    int b = idx >> 10, j = idx & 1023;
    float hd = g_h[idx] * g_gammaH[(size_t)t*BV*HV + idx];
    int base = b*3*HV + j;
    float r = 1.f / (1.f + expf(-(g_gi[base]        + g_gh[base])));
    float z = 1.f / (1.f + expf(-(g_gi[base + HV]   + g_gh[base + HV])));
    float n = tanhf(g_gi[base + 2*HV] + r * g_gh[base + 2*HV]);
    float hn = (1.f - z) * n + z * hd;
    g_h[idx] = hn;
    if (t + 1 < TV)
        ASWZ_H[AOFF_G1 + aidx16(b, j, 64)] =
            f2h(hn * g_gammaH[(size_t)(t+1)*BV*HV + idx]);
    if (hfin) hfin[idx] = hn;
}

__global__ void final_k(float* __restrict__ out) {
    __shared__ float s[TV];
    int t = threadIdx.x;  // 64 threads
    float acc = 0.f;
    for (int i = 0; i < NB2; i++) acc += g_lossPart[t*NB2 + i];
    s[t] = acc / (g_msum[t] + 1e-12f);
    __syncthreads();
    if (t == 0) {
        float L = 0.f;
        for (int i = 0; i < TV; i++) L += s[i];
        out[OFF_LOSS]     = L;
        out[OFF_LOSS + 1] = 0.f;  // kl_loss
    }
}

// ---------------- launch ----------------

extern "C" void kernel_launch(void* const* d_in, const int* in_sizes, int n_in,
                              void* d_out, int out_size) {
    const float* x      = (const float*)d_in[0];
    const float* mask   = (const float*)d_in[1];
    const float* deltas = (const float*)d_in[2];
    const float* h0     = (const float*)d_in[3];
    const float* Wdh    = (const float*)d_in[4];
    const float* bdh    = (const float*)d_in[5];
    const float* Wdx    = (const float*)d_in[6];
    const float* bdx    = (const float*)d_in[7];
    const float* Wh     = (const float*)d_in[8];
    const float* bh     = (const float*)d_in[9];
    const float* Wfr    = (const float*)d_in[10];
    const float* bfr    = (const float*)d_in[11];
    const float* Wwc    = (const float*)d_in[12];
    const float* bwc    = (const float*)d_in[13];
    const float* Wih    = (const float*)d_in[14];
    const float* bih    = (const float*)d_in[15];
    const float* Whh    = (const float*)d_in[16];
    const float* bhh    = (const float*)d_in[17];

    float* out      = (float*)d_out;
    float* ximp_out = out;
    float* rec_out  = out + OFF_REC;
    float* hfin     = out + OFF_HFIN;

    msum_k<<<TV, 256>>>(mask);

    // Pre-swizzle weights (B operands) to fp16 fragment layout
    swz_k<<<(3328*1024)/256, 256>>>(BOFF_G1, 3328, 1024, BL_G1{Wh, Whh});
    swz_k<<<(3072*512 )/256, 256>>>(BOFF_G3, 3072, 512,  BL_G3{Wih});
    swz_k<<<(256*256  )/256, 256>>>(BOFF_G2, 256,  256,  BL_G2{Wfr});
    swz_k<<<(1024*256 )/256, 256>>>(BOFF_P1, 1024, 256,  BL_P1{Wdh});
    swz_k<<<(256*512  )/256, 256>>>(BOFF_P2, 256,  512,  BL_P2{Wwc});

    // Pre-swizzle A operands for P1/P2 and G3 mask half
    swzA_P1_k<<<(32768*256)/256, 256>>>(deltas);
    swzA_P2_k<<<(32768*512)/256, 256>>>(deltas, mask, Wdx, bdx);
    swzA_G3m_k<<<(TV*BV*FV)/256, 256>>>(mask);

    // P1: gammaH, M=32768, N=1024, K=256
    tgemm4_k<64,128,32,32><<<dim3(1024/128, 32768/64), 256>>>(
        FV, AOFF_P1, BOFF_P1, EP_P1{bdh});

    // h init (needs gammaH[0])
    hAinit_k<<<(BV*HV)/256, 256>>>(h0);

    // P2: beta, M=32768, N=256, K=512
    tgemm4_k<64,128,32,32><<<dim3(256/128, 32768/64), 256>>>(
        2*FV, AOFF_P2, BOFF_P2, EP_P2{bwc});

    for (int t = 0; t < TV; t++) {
        // G1: [x_h | gh], M=512, N=3328, K=1024 -> 208 blocks
        tgemm4_k<64,128,32,32><<<dim3(3328/128, 512/64), 256>>>(
            HV, AOFF_G1, BOFF_G1, EP_G1{bh, bhh, x, mask, t});

        // G2: xu + combine/imputation/loss, M=512, N=256, K=256 -> 32 blocks
        tgemm4_k<64,64,32,16><<<dim3(256/64, 512/64), 256>>>(
            FV, AOFF_G2, BOFF_G2, EP_G2{bfr, x, mask, rec_out, ximp_out, t});

        // G3: gi, M=512, N=3072, K=512 -> 192 blocks
        tgemm4_k<64,128,32,32><<<dim3(3072/128, 512/64), 256>>>(
            2*FV, AOFF_G3 + t*AG3_STRIDE, BOFF_G3, EP_G3{bih});

        // GRU elementwise update (+ next step's swizzled A)
        gru_k<<<(BV*HV)/256, 256>>>(t, (t == TV-1) ? hfin : nullptr);
    }

    final_k<<<1, TV>>>(out);
}

// round 14
// speedup vs baseline: 1.6606x; 1.1530x over previous
#include <cuda_runtime.h>
#include <cuda_fp16.h>
#include <math.h>
#include <stdint.h>

// Problem constants
#define BV 512
#define TV 64
#define FV 256
#define HV 1024

// Output layout: x_imp [B,T,F] | reconstruction [B,T,F] | h_fin [B,H] | x_loss | kl_loss
#define OFF_REC   (BV*TV*FV)
#define OFF_HFIN  (2*BV*TV*FV)
#define OFF_LOSS  (2*BV*TV*FV + BV*HV)

#define NB2 32   // loss partial tiles per step

// ---------------- scratch ----------------
__device__ float g_h[BV*HV];
__device__ float g_xh[BV*FV];
__device__ float g_gh[BV*3*HV];
__device__ float g_gi[BV*3*HV];
__device__ float g_gammaH[(size_t)TV*BV*HV];
__device__ float g_beta[(size_t)TV*BV*FV];
__device__ float g_msum[TV];
__device__ float g_lossPart[TV*NB2];

// ---- pre-swizzled fp16 B (weights); uint2 = one (n8,k16) lane fragment ----
#define SZB(N,K) ((N)*(K)/4)
#define BOFF_G1 0
#define BOFF_G3 (BOFF_G1 + SZB(3328,1024))
#define BOFF_G2 (BOFF_G3 + SZB(3072,512))
#define BOFF_P1 (BOFF_G2 + SZB(256,256))
#define BOFF_P2 (BOFF_P1 + SZB(1024,256))
#define BSWZ_TOTAL (BOFF_P2 + SZB(256,512))
__device__ uint2 g_Bswz[BSWZ_TOTAL];

// ---- pre-swizzled fp16 A (activations); offsets in ELEMENT (halfword) units ----
#define AOFF_G1 0                                   // 512x1024
#define AOFF_G2 (AOFF_G1 + BV*HV)                   // 512x256
#define AOFF_G3 (AOFF_G2 + BV*FV)                   // 64 slices of 512x512
#define AG3_STRIDE (BV*2*FV)
#define AOFF_P1 (AOFF_G3 + TV*AG3_STRIDE)           // 32768x256
#define AOFF_P2 (AOFF_P1 + TV*BV*FV)                // 32768x512
#define ASWZ_TOTAL (AOFF_P2 + TV*BV*2*FV)
__device__ uint4 g_Aswz4[ASWZ_TOTAL/8];
#define ASWZ_H ((uint16_t*)g_Aswz4)
#define ASWZ_W ((uint32_t*)g_Aswz4)

__device__ __forceinline__ uint16_t f2h(float f) {
    return __half_as_ushort(__float2half_rn(f));
}
__device__ __forceinline__ uint32_t pack2h(float a, float b) {
    return (uint32_t)f2h(a) | ((uint32_t)f2h(b) << 16);
}

// element index of A(m,k) in fp16 m16n8k16 fragment-native layout (KT16 = K/16)
__device__ __forceinline__ int aidx16(int m, int k, int KT16) {
    int r = m & 15, c = k & 15;
    int lane = (r & 7)*4 + ((c & 7) >> 1);
    int reg  = (r >> 3) + ((c >> 3) << 1);
    return ((((m >> 4)*KT16 + (k >> 4))*32 + lane)*4 + reg)*2 + (c & 1);
}
// element index of B(n,k) in fp16 m16n8k16 fragment-native layout
__device__ __forceinline__ int bidx16(int n, int k, int KT16) {
    int c = k & 15;
    int lane = (n & 7)*4 + ((c & 7) >> 1);
    int reg  = (c >> 3) & 1;
    return ((((n >> 3)*KT16 + (k >> 4))*32 + lane)*2 + reg)*2 + (k & 1);
}

// ---------------- weight pre-swizzle (paired k: one u32 store per 2 elements) ----------------
template<class BL>
__global__ void swz_k(int boff, int N, int K, BL bl) {
    int idx = blockIdx.x * 256 + threadIdx.x;   // over N*K/2
    if (idx >= N*(K >> 1)) return;
    int n = idx / (K >> 1), k = (idx % (K >> 1)) * 2;
    uint32_t* d = (uint32_t*)(g_Bswz + boff);
    d[bidx16(n, k, K >> 4) >> 1] = pack2h(bl(n, k), bl(n, k + 1));
}

// ------------- fp16 m16n8k16 GEMM: pre-swizzled A via smem, B direct LDG. BK = 64 -------------
template<int BM,int BN,int WM,int WN,class EP>
__global__ __launch_bounds__(256, 2)
void tgemm4_k(int K, int aoff, int boff, EP ep) {
    constexpr int WARPS_M = BM/WM, WARPS_N = BN/WN;
    static_assert(WARPS_M*WARPS_N == 8, "need 8 warps");
    constexpr int MI = WM/16, NI = WN/8;
    constexpr int KT = 4;                         // k16-tiles per BK=64 tile
    constexpr int TILE4 = (BM/16)*KT*32;          // uint4 per A tile (512 for BM=64)
    constexpr int CP = TILE4/256;

    __shared__ uint4 As[2][TILE4];
    __shared__ float red[256];

    const int KT16 = K >> 4;
    const int tid = threadIdx.x, lane = tid & 31, wid = tid >> 5;
    const int wm = (wid % WARPS_M)*WM, wn = (wid / WARPS_M)*WN;
    const int gid = lane >> 2, tig = lane & 3;
    const int bm = blockIdx.y*BM, bn = blockIdx.x*BN;
    const int mtBase = bm >> 4;
    const int ntBase = (bn + wn) >> 3;
    const int wmt = wm >> 4;

    const uint4* __restrict__ Ag = (const uint4*)(ASWZ_H + aoff);
    const uint2* __restrict__ Bg = g_Bswz + boff;

    float acc[MI][NI][4];
    #pragma unroll
    for (int mi = 0; mi < MI; mi++)
        #pragma unroll
        for (int ni = 0; ni < NI; ni++)
            #pragma unroll
            for (int c = 0; c < 4; c++) acc[mi][ni][c] = 0.f;

    uint4 ar[CP];
    auto ldA = [&](int kt0) {
        #pragma unroll
        for (int i = 0; i < CP; i++) {
            int e = tid + i*256;
            int mtl = e / (KT*32), rem = e % (KT*32);
            ar[i] = Ag[((mtBase + mtl)*KT16 + kt0 + rem/32)*32 + (rem & 31)];
        }
    };
    auto stA = [&](int buf) {
        #pragma unroll
        for (int i = 0; i < CP; i++) As[buf][tid + i*256] = ar[i];
    };

    ldA(0); stA(0);
    __syncthreads();

    int cur = 0;
    for (int kt0 = 0; kt0 < KT16; kt0 += KT) {
        const bool more = (kt0 + KT) < KT16;
        // B fragments for this tile: direct LDG.64 from pre-swizzled global
        uint2 bf[NI][KT];
        #pragma unroll
        for (int ni = 0; ni < NI; ni++)
            #pragma unroll
            for (int kk = 0; kk < KT; kk++)
                bf[ni][kk] = Bg[((ntBase + ni)*KT16 + kt0 + kk)*32 + lane];
        if (more) ldA(kt0 + KT);

        #pragma unroll
        for (int kk = 0; kk < KT; kk++) {
            uint4 av[MI];
            #pragma unroll
            for (int mi = 0; mi < MI; mi++)
                av[mi] = As[cur][((wmt + mi)*KT + kk)*32 + lane];
            #pragma unroll
            for (int mi = 0; mi < MI; mi++)
                #pragma unroll
                for (int ni = 0; ni < NI; ni++)
                    asm volatile(
                        "mma.sync.aligned.m16n8k16.row.col.f32.f16.f16.f32 "
                        "{%0,%1,%2,%3}, {%4,%5,%6,%7}, {%8,%9}, {%0,%1,%2,%3};"
                        : "+f"(acc[mi][ni][0]), "+f"(acc[mi][ni][1]),
                          "+f"(acc[mi][ni][2]), "+f"(acc[mi][ni][3])
                        : "r"(av[mi].x), "r"(av[mi].y), "r"(av[mi].z), "r"(av[mi].w),
                          "r"(bf[ni][kk].x), "r"(bf[ni][kk].y));
        }
        if (more) stA(cur ^ 1);
        __syncthreads();
        cur ^= 1;
    }

    float rsum = 0.f;
    #pragma unroll
    for (int mi = 0; mi < MI; mi++) {
        #pragma unroll
        for (int ni = 0; ni < NI; ni++) {
            int gm0 = bm + wm + mi*16 + gid;
            int gn0 = bn + wn + ni*8 + tig*2;
            rsum += ep(gm0,     gn0,     acc[mi][ni][0]);
            rsum += ep(gm0,     gn0 + 1, acc[mi][ni][1]);
            rsum += ep(gm0 + 8, gn0,     acc[mi][ni][2]);
            rsum += ep(gm0 + 8, gn0 + 1, acc[mi][ni][3]);
        }
    }

    if constexpr (EP::RED) {
        red[tid] = rsum;
        __syncthreads();
        for (int s = 128; s > 0; s >>= 1) {
            if (tid < s) red[tid] += red[tid + s];
            __syncthreads();
        }
        if (tid == 0) {
            int lin = blockIdx.y * gridDim.x + blockIdx.x;
            ep.store_partial(lin, red[0]);
        }
    }
}

// ---------------- B-side scalar loaders (used only by swz_k) ----------------

struct BL_P1 {
    const float* Wdh;
    __device__ float operator()(int n, int k) const { return Wdh[n*FV + k]; }
};
struct BL_P2 {
    const float* Wwc;
    __device__ float operator()(int n, int k) const { return Wwc[n*(2*FV) + k]; }
};
struct BL_G1 {
    const float* Wh; const float* Whh;
    __device__ float operator()(int n, int k) const {
        return (n < FV) ? Wh[n*HV + k] : Whh[(n - FV)*HV + k];
    }
};
struct BL_G2 {
    const float* Wfr;
    __device__ float operator()(int n, int k) const {
        return (n == k) ? 0.f : Wfr[n*FV + k];
    }
};
struct BL_G3 {
    const float* Wih;
    __device__ float operator()(int n, int k) const { return Wih[n*(2*FV) + k]; }
};

// ---------------- A-side pre-swizzle kernels (paired k: one u32 store per 2 elems) ----------------

__global__ void swzA_P1_k(const float* __restrict__ deltas) {
    int idx = blockIdx.x * 256 + threadIdx.x;   // 32768*128 pairs
    int m = idx >> 7, k = (idx & 127) * 2;
    int t = m >> 9, b = m & 511;
    const float* src = &deltas[(b*TV + t)*FV + k];
    ASWZ_W[(AOFF_P1 + aidx16(m, k, 16)) >> 1] = pack2h(src[0], src[1]);
}

__global__ void swzA_P2_k(const float* __restrict__ deltas, const float* __restrict__ mask,
                          const float* __restrict__ Wdx, const float* __restrict__ bdx) {
    int idx = blockIdx.x * 256 + threadIdx.x;   // 32768*256 pairs
    int m = idx >> 8, k = (idx & 255) * 2;
    int t = m >> 9, b = m & 511;
    float v0, v1;
    if (k < FV) {
        float d0 = deltas[(b*TV + t)*FV + k];
        float d1 = deltas[(b*TV + t)*FV + k + 1];
        v0 = expf(-fmaxf(d0 * Wdx[k*FV + k] + bdx[k], 0.f));
        v1 = expf(-fmaxf(d1 * Wdx[(k+1)*FV + (k+1)] + bdx[k+1], 0.f));
    } else {
        v0 = mask[(b*TV + t)*FV + (k - FV)];
        v1 = mask[(b*TV + t)*FV + (k - FV) + 1];
    }
    ASWZ_W[(AOFF_P2 + aidx16(m, k, 32)) >> 1] = pack2h(v0, v1);
}

__global__ void swzA_G3m_k(const float* __restrict__ mask) {
    int idx = blockIdx.x * 256 + threadIdx.x;   // 64*512*128 pairs
    int t = idx >> 16, b = (idx >> 7) & 511, f = (idx & 127) * 2;
    const float* src = &mask[(b*TV + t)*FV + f];
    ASWZ_W[(AOFF_G3 + t*AG3_STRIDE + aidx16(b, FV + f, 32)) >> 1] =
        pack2h(src[0], src[1]);
}

// h init: plain h0 + swizzled fp16 h0*gammaH[0] (run after P1 GEMM)
__global__ void hAinit_k(const float* __restrict__ h0) {
    int idx = blockIdx.x * 256 + threadIdx.x;   // B*H/2 pairs
    int b = idx >> 9, j = (idx & 511) * 2;
    int e = b*HV + j;
    float ha = h0[e], hb = h0[e+1];
    g_h[e] = ha; g_h[e+1] = hb;
    ASWZ_W[(AOFF_G1 + aidx16(b, j, 64)) >> 1] =
        pack2h(ha * g_gammaH[e], hb * g_gammaH[e+1]);
}

// ---------------- epilogues ----------------

struct EP_P1 {
    const float* bdh;
    static constexpr bool RED = false;
    __device__ float operator()(int m, int n, float v) const {
        g_gammaH[(size_t)m*HV + n] = expf(-fmaxf(v + bdh[n], 0.f));
        return 0.f;
    }
    __device__ void store_partial(int, float) const {}
};
struct EP_P2 {
    const float* bwc;
    static constexpr bool RED = false;
    __device__ float operator()(int m, int n, float v) const {
        g_beta[(size_t)m*FV + n] = v + bwc[n];
        return 0.f;
    }
    __device__ void store_partial(int, float) const {}
};
struct EP_G1 {
    const float* bh; const float* bhh; const float* x; const float* mask; int t;
    static constexpr bool RED = false;
    __device__ float operator()(int m, int n, float v) const {
        if (n < FV) {
            float xh = v + bh[n];
            g_xh[m*FV + n] = xh;
            int idx = (m*TV + t)*FV + n;
            float mt = mask[idx];
            float xr = mt * x[idx] + (1.f - mt) * xh;
            ASWZ_H[AOFF_G2 + aidx16(m, n, 16)] = f2h(xr);
        } else {
            g_gh[m*3*HV + (n - FV)] = v + bhh[n - FV];
        }
        return 0.f;
    }
    __device__ void store_partial(int, float) const {}
};
struct EP_G2 {
    const float* bfr; const float* x; const float* mask;
    float* rec; float* ximp; int t;
    static constexpr bool RED = true;
    __device__ float operator()(int m, int n, float v) const {
        float xu = v + bfr[n];
        float xh = g_xh[m*FV + n];
        float be = g_beta[(size_t)t*BV*FV + m*FV + n];
        float xc = be * xu + (1.f - be) * xh;
        int idx = (m*TV + t)*FV + n;
        float mt = mask[idx], xt = x[idx];
        rec[idx]  = xc;
        float xi = mt * xt + (1.f - mt) * xc;
        ximp[idx] = xi;
        ASWZ_H[AOFF_G3 + t*AG3_STRIDE + aidx16(m, n, 32)] = f2h(xi);
        return fabsf(xc - xt) * mt;
    }
    __device__ void store_partial(int lin, float v) const {
        g_lossPart[t*NB2 + lin] = v;
    }
};
struct EP_G3 {
    const float* bih;
    static constexpr bool RED = false;
    __device__ float operator()(int m, int n, float v) const {
        g_gi[m*3*HV + n] = v + bih[n];
        return 0.f;
    }
    __device__ void store_partial(int, float) const {}
};

// ---------------- elementwise kernels ----------------

__global__ void msum_k(const float* __restrict__ mask) {
    int t = blockIdx.x;
    float s = 0.f;
    for (int i = threadIdx.x; i < BV*FV; i += 256) {
        int b = i >> 8, f = i & 255;
        s += mask[(b*TV + t)*FV + f];
    }
    __shared__ float red[256];
    red[threadIdx.x] = s;
    __syncthreads();
    for (int st = 128; st > 0; st >>= 1) {
        if (threadIdx.x < st) red[threadIdx.x] += red[threadIdx.x + st];
        __syncthreads();
    }
    if (threadIdx.x == 0) g_msum[t] = red[0];
}

// GRU update (paired j): computes 2 elements, writes one u32 into swizzled A
__global__ void gru_k(int t, float* __restrict__ hfin) {
    int idx = blockIdx.x * blockDim.x + threadIdx.x;  // B*H/2 pairs
    int b = idx >> 9, j = (idx & 511) * 2;
    int e = b*HV + j;
    float hn2[2];
    #pragma unroll
    for (int u = 0; u < 2; u++) {
        float hd = g_h[e+u] * g_gammaH[(size_t)t*BV*HV + e+u];
        int base = b*3*HV + j + u;
        float r = 1.f / (1.f + expf(-(g_gi[base]        + g_gh[base])));
        float z = 1.f / (1.f + expf(-(g_gi[base + HV]   + g_gh[base + HV])));
        float n = tanhf(g_gi[base + 2*HV] + r * g_gh[base + 2*HV]);
        float hn = (1.f - z) * n + z * hd;
        g_h[e+u] = hn;
        hn2[u] = hn;
        if (hfin) hfin[e+u] = hn;
    }
    if (t + 1 < TV)
        ASWZ_W[(AOFF_G1 + aidx16(b, j, 64)) >> 1] =
            pack2h(hn2[0] * g_gammaH[(size_t)(t+1)*BV*HV + e],
                   hn2[1] * g_gammaH[(size_t)(t+1)*BV*HV + e + 1]);
}

__global__ void final_k(float* __restrict__ out) {
    __shared__ float s[TV];
    int t = threadIdx.x;  // 64 threads
    float acc = 0.f;
    for (int i = 0; i < NB2; i++) acc += g_lossPart[t*NB2 + i];
    s[t] = acc / (g_msum[t] + 1e-12f);
    __syncthreads();
    if (t == 0) {
        float L = 0.f;
        for (int i = 0; i < TV; i++) L += s[i];
        out[OFF_LOSS]     = L;
        out[OFF_LOSS + 1] = 0.f;  // kl_loss
    }
}

// ---------------- launch ----------------

extern "C" void kernel_launch(void* const* d_in, const int* in_sizes, int n_in,
                              void* d_out, int out_size) {
    const float* x      = (const float*)d_in[0];
    const float* mask   = (const float*)d_in[1];
    const float* deltas = (const float*)d_in[2];
    const float* h0     = (const float*)d_in[3];
    const float* Wdh    = (const float*)d_in[4];
    const float* bdh    = (const float*)d_in[5];
    const float* Wdx    = (const float*)d_in[6];
    const float* bdx    = (const float*)d_in[7];
    const float* Wh     = (const float*)d_in[8];
    const float* bh     = (const float*)d_in[9];
    const float* Wfr    = (const float*)d_in[10];
    const float* bfr    = (const float*)d_in[11];
    const float* Wwc    = (const float*)d_in[12];
    const float* bwc    = (const float*)d_in[13];
    const float* Wih    = (const float*)d_in[14];
    const float* bih    = (const float*)d_in[15];
    const float* Whh    = (const float*)d_in[16];
    const float* bhh    = (const float*)d_in[17];

    float* out      = (float*)d_out;
    float* ximp_out = out;
    float* rec_out  = out + OFF_REC;
    float* hfin     = out + OFF_HFIN;

    msum_k<<<TV, 256>>>(mask);

    // Pre-swizzle weights (B operands) to fp16 fragment layout (paired stores)
    swz_k<<<(3328*1024/2)/256, 256>>>(BOFF_G1, 3328, 1024, BL_G1{Wh, Whh});
    swz_k<<<(3072*512 /2)/256, 256>>>(BOFF_G3, 3072, 512,  BL_G3{Wih});
    swz_k<<<(256*256  /2)/256, 256>>>(BOFF_G2, 256,  256,  BL_G2{Wfr});
    swz_k<<<(1024*256 /2)/256, 256>>>(BOFF_P1, 1024, 256,  BL_P1{Wdh});
    swz_k<<<(256*512  /2)/256, 256>>>(BOFF_P2, 256,  512,  BL_P2{Wwc});

    // Pre-swizzle A operands for P1/P2 and G3 mask half (paired stores)
    swzA_P1_k<<<(32768*128)/256, 256>>>(deltas);
    swzA_P2_k<<<(32768*256)/256, 256>>>(deltas, mask, Wdx, bdx);
    swzA_G3m_k<<<(TV*BV*128)/256, 256>>>(mask);

    // P1: gammaH, M=32768, N=1024, K=256
    tgemm4_k<64,128,32,32><<<dim3(1024/128, 32768/64), 256>>>(
        FV, AOFF_P1, BOFF_P1, EP_P1{bdh});

    // h init (needs gammaH[0])
    hAinit_k<<<(BV*HV/2)/256, 256>>>(h0);

    // P2: beta, M=32768, N=256, K=512
    tgemm4_k<64,128,32,32><<<dim3(256/128, 32768/64), 256>>>(
        2*FV, AOFF_P2, BOFF_P2, EP_P2{bwc});

    for (int t = 0; t < TV; t++) {
        // G1: [x_h | gh], M=512, N=3328, K=1024 -> 208 blocks
        tgemm4_k<64,128,32,32><<<dim3(3328/128, 512/64), 256>>>(
            HV, AOFF_G1, BOFF_G1, EP_G1{bh, bhh, x, mask, t});

        // G2: xu + combine/imputation/loss, M=512, N=256, K=256 -> 32 blocks
        tgemm4_k<64,64,32,16><<<dim3(256/64, 512/64), 256>>>(
            FV, AOFF_G2, BOFF_G2, EP_G2{bfr, x, mask, rec_out, ximp_out, t});

        // G3: gi, M=512, N=3072, K=512 -> 192 blocks
        tgemm4_k<64,128,32,32><<<dim3(3072/128, 512/64), 256>>>(
            2*FV, AOFF_G3 + t*AG3_STRIDE, BOFF_G3, EP_G3{bih});

        // GRU elementwise update (+ next step's swizzled A)
        gru_k<<<(BV*HV/2)/256, 256>>>(t, (t == TV-1) ? hfin : nullptr);
    }

    final_k<<<1, TV>>>(out);
}

// round 16
// speedup vs baseline: 1.6904x; 1.0179x over previous
#include <cuda_runtime.h>
#include <cuda_fp16.h>
#include <math.h>
#include <stdint.h>

// Problem constants
#define BV 512
#define TV 64
#define FV 256
#define HV 1024

#define OFF_REC   (BV*TV*FV)
#define OFF_HFIN  (2*BV*TV*FV)
#define OFF_LOSS  (2*BV*TV*FV + BV*HV)

#define NB2 32   // loss partial tiles per step

// ---------------- scratch ----------------
__device__ float g_h[BV*HV];
__device__ float g_xh[BV*FV];
__device__ float g_gh[BV*3*HV];
__device__ float g_gi[BV*3*HV];
__device__ float g_gammaH[(size_t)TV*BV*HV];
__device__ float g_beta[(size_t)TV*BV*FV];
__device__ float g_msum[TV];
__device__ float g_lossPart[TV*NB2];

// ---- pre-swizzled fp16 B (weights); uint2 = one (n8,k16) lane fragment ----
#define SZB(N,K) ((N)*(K)/4)
#define BOFF_G1 0
#define BOFF_G3 (BOFF_G1 + SZB(3328,1024))
#define BOFF_G2 (BOFF_G3 + SZB(3072,512))
#define BOFF_P1 (BOFF_G2 + SZB(256,256))
#define BOFF_P2 (BOFF_P1 + SZB(1024,256))
#define BSWZ_TOTAL (BOFF_P2 + SZB(256,512))
__device__ uint2 g_Bswz[BSWZ_TOTAL];

// ---- pre-swizzled fp16 A (activations); offsets in ELEMENT (halfword) units ----
#define AOFF_G1 0                                   // 512x1024
#define AOFF_G2 (AOFF_G1 + BV*HV)                   // 512x256
#define AOFF_G3 (AOFF_G2 + BV*FV)                   // 64 slices of 512x512
#define AG3_STRIDE (BV*2*FV)
#define AOFF_P1 (AOFF_G3 + TV*AG3_STRIDE)           // 32768x256
#define AOFF_P2 (AOFF_P1 + TV*BV*FV)                // 32768x512
#define ASWZ_TOTAL (AOFF_P2 + TV*BV*2*FV)
__device__ uint4 g_Aswz4[ASWZ_TOTAL/8];
#define ASWZ_H ((uint16_t*)g_Aswz4)
#define ASWZ_W ((uint32_t*)g_Aswz4)

__device__ __forceinline__ uint16_t f2h(float f) {
    return __half_as_ushort(__float2half_rn(f));
}
__device__ __forceinline__ uint32_t pack2h(float a, float b) {
    return (uint32_t)f2h(a) | ((uint32_t)f2h(b) << 16);
}

// PDL primitives (sm_90+; safe no-ops without PDL launch attrs)
__device__ __forceinline__ void gdc_wait() {
    asm volatile("griddepcontrol.wait;" ::: "memory");
}
__device__ __forceinline__ void gdc_launch() {
    asm volatile("griddepcontrol.launch_dependents;");
}

// element index of A(m,k) in fp16 m16n8k16 fragment-native layout (KT16 = K/16)
__device__ __forceinline__ int aidx16(int m, int k, int KT16) {
    int r = m & 15, c = k & 15;
    int lane = (r & 7)*4 + ((c & 7) >> 1);
    int reg  = (r >> 3) + ((c >> 3) << 1);
    return ((((m >> 4)*KT16 + (k >> 4))*32 + lane)*4 + reg)*2 + (c & 1);
}
// element index of B(n,k) in fp16 m16n8k16 fragment-native layout
__device__ __forceinline__ int bidx16(int n, int k, int KT16) {
    int c = k & 15;
    int lane = (n & 7)*4 + ((c & 7) >> 1);
    int reg  = (c >> 3) & 1;
    return ((((n >> 3)*KT16 + (k >> 4))*32 + lane)*2 + reg)*2 + (k & 1);
}

// ---------------- weight pre-swizzle (paired k: one u32 store per 2 elements) ----------------
template<class BL>
__global__ void swz_k(int boff, int N, int K, BL bl) {
    int idx = blockIdx.x * 256 + threadIdx.x;   // over N*K/2
    if (idx >= N*(K >> 1)) return;
    int n = idx / (K >> 1), k = (idx % (K >> 1)) * 2;
    uint32_t* d = (uint32_t*)(g_Bswz + boff);
    d[bidx16(n, k, K >> 4) >> 1] = pack2h(bl(n, k), bl(n, k + 1));
}

// ------------- fp16 m16n8k16 GEMM: pre-swizzled A via smem, B direct LDG. BK = 64 -------------
template<int BM,int BN,int WM,int WN,class EP>
__global__ __launch_bounds__(256, 2)
void tgemm4_k(int K, int aoff, int boff, EP ep) {
    constexpr int WARPS_M = BM/WM, WARPS_N = BN/WN;
    static_assert(WARPS_M*WARPS_N == 8, "need 8 warps");
    constexpr int MI = WM/16, NI = WN/8;
    constexpr int KT = 4;                         // k16-tiles per BK=64 tile
    constexpr int TILE4 = (BM/16)*KT*32;          // uint4 per A tile (512 for BM=64)
    constexpr int CP = TILE4/256;

    __shared__ uint4 As[2][TILE4];
    __shared__ float red[256];

    const int KT16 = K >> 4;
    const int tid = threadIdx.x, lane = tid & 31, wid = tid >> 5;
    const int wm = (wid % WARPS_M)*WM, wn = (wid / WARPS_M)*WN;
    const int gid = lane >> 2, tig = lane & 3;
    const int bm = blockIdx.y*BM, bn = blockIdx.x*BN;
    const int mtBase = bm >> 4;
    const int ntBase = (bn + wn) >> 3;
    const int wmt = wm >> 4;

    const uint4* __restrict__ Ag = (const uint4*)(ASWZ_H + aoff);
    const uint2* __restrict__ Bg = g_Bswz + boff;

    float acc[MI][NI][4];
    #pragma unroll
    for (int mi = 0; mi < MI; mi++)
        #pragma unroll
        for (int ni = 0; ni < NI; ni++)
            #pragma unroll
            for (int c = 0; c < 4; c++) acc[mi][ni][c] = 0.f;

    uint4 ar[CP];
    auto ldA = [&](int kt0) {
        #pragma unroll
        for (int i = 0; i < CP; i++) {
            int e = tid + i*256;
            int mtl = e / (KT*32), rem = e % (KT*32);
            ar[i] = Ag[((mtBase + mtl)*KT16 + kt0 + rem/32)*32 + (rem & 31)];
        }
    };
    auto stA = [&](int buf) {
        #pragma unroll
        for (int i = 0; i < CP; i++) As[buf][tid + i*256] = ar[i];
    };

    // PDL: block may start before predecessor fully retires; wait before first
    // read of predecessor-produced data (A operand).
    gdc_wait();

    ldA(0); stA(0);
    __syncthreads();

    int cur = 0;
    for (int kt0 = 0; kt0 < KT16; kt0 += KT) {
        const bool more = (kt0 + KT) < KT16;
        uint2 bf[NI][KT];
        #pragma unroll
        for (int ni = 0; ni < NI; ni++)
            #pragma unroll
            for (int kk = 0; kk < KT; kk++)
                bf[ni][kk] = Bg[((ntBase + ni)*KT16 + kt0 + kk)*32 + lane];
        if (more) ldA(kt0 + KT);

        #pragma unroll
        for (int kk = 0; kk < KT; kk++) {
            uint4 av[MI];
            #pragma unroll
            for (int mi = 0; mi < MI; mi++)
                av[mi] = As[cur][((wmt + mi)*KT + kk)*32 + lane];
            #pragma unroll
            for (int mi = 0; mi < MI; mi++)
                #pragma unroll
                for (int ni = 0; ni < NI; ni++)
                    asm volatile(
                        "mma.sync.aligned.m16n8k16.row.col.f32.f16.f16.f32 "
                        "{%0,%1,%2,%3}, {%4,%5,%6,%7}, {%8,%9}, {%0,%1,%2,%3};"
                        : "+f"(acc[mi][ni][0]), "+f"(acc[mi][ni][1]),
                          "+f"(acc[mi][ni][2]), "+f"(acc[mi][ni][3])
                        : "r"(av[mi].x), "r"(av[mi].y), "r"(av[mi].z), "r"(av[mi].w),
                          "r"(bf[ni][kk].x), "r"(bf[ni][kk].y));
        }
        if (more) stA(cur ^ 1);
        __syncthreads();
        cur ^= 1;
    }

    float rsum = 0.f;
    #pragma unroll
    for (int mi = 0; mi < MI; mi++) {
        #pragma unroll
        for (int ni = 0; ni < NI; ni++) {
            int gm0 = bm + wm + mi*16 + gid;
            int gn0 = bn + wn + ni*8 + tig*2;
            rsum += ep(gm0,     gn0,     acc[mi][ni][0]);
            rsum += ep(gm0,     gn0 + 1, acc[mi][ni][1]);
            rsum += ep(gm0 + 8, gn0,     acc[mi][ni][2]);
            rsum += ep(gm0 + 8, gn0 + 1, acc[mi][ni][3]);
        }
    }

    if constexpr (EP::RED) {
        red[tid] = rsum;
        __syncthreads();
        for (int s = 128; s > 0; s >>= 1) {
            if (tid < s) red[tid] += red[tid + s];
            __syncthreads();
        }
        if (tid == 0) {
            int lin = blockIdx.y * gridDim.x + blockIdx.x;
            ep.store_partial(lin, red[0]);
        }
    }
    // PDL: all consumed stores done — allow dependent kernel to launch.
    gdc_launch();
}

// ---------------- B-side scalar loaders (used only by swz_k) ----------------

struct BL_P1 {
    const float* Wdh;
    __device__ float operator()(int n, int k) const { return Wdh[n*FV + k]; }
};
struct BL_P2 {
    const float* Wwc;
    __device__ float operator()(int n, int k) const { return Wwc[n*(2*FV) + k]; }
};
struct BL_G1 {
    const float* Wh; const float* Whh;
    __device__ float operator()(int n, int k) const {
        return (n < FV) ? Wh[n*HV + k] : Whh[(n - FV)*HV + k];
    }
};
struct BL_G2 {
    const float* Wfr;
    __device__ float operator()(int n, int k) const {
        return (n == k) ? 0.f : Wfr[n*FV + k];
    }
};
struct BL_G3 {
    const float* Wih;
    __device__ float operator()(int n, int k) const { return Wih[n*(2*FV) + k]; }
};

// ---------------- A-side pre-swizzle kernels (paired k) ----------------

__global__ void swzA_P1_k(const float* __restrict__ deltas) {
    int idx = blockIdx.x * 256 + threadIdx.x;   // 32768*128 pairs
    int m = idx >> 7, k = (idx & 127) * 2;
    int t = m >> 9, b = m & 511;
    const float* src = &deltas[(b*TV + t)*FV + k];
    ASWZ_W[(AOFF_P1 + aidx16(m, k, 16)) >> 1] = pack2h(src[0], src[1]);
}

__global__ void swzA_P2_k(const float* __restrict__ deltas, const float* __restrict__ mask,
                          const float* __restrict__ Wdx, const float* __restrict__ bdx) {
    int idx = blockIdx.x * 256 + threadIdx.x;   // 32768*256 pairs
    int m = idx >> 8, k = (idx & 255) * 2;
    int t = m >> 9, b = m & 511;
    float v0, v1;
    if (k < FV) {
        float d0 = deltas[(b*TV + t)*FV + k];
        float d1 = deltas[(b*TV + t)*FV + k + 1];
        v0 = expf(-fmaxf(d0 * Wdx[k*FV + k] + bdx[k], 0.f));
        v1 = expf(-fmaxf(d1 * Wdx[(k+1)*FV + (k+1)] + bdx[k+1], 0.f));
    } else {
        v0 = mask[(b*TV + t)*FV + (k - FV)];
        v1 = mask[(b*TV + t)*FV + (k - FV) + 1];
    }
    ASWZ_W[(AOFF_P2 + aidx16(m, k, 32)) >> 1] = pack2h(v0, v1);
}

__global__ void swzA_G3m_k(const float* __restrict__ mask) {
    int idx = blockIdx.x * 256 + threadIdx.x;   // 64*512*128 pairs
    int t = idx >> 16, b = (idx >> 7) & 511, f = (idx & 127) * 2;
    const float* src = &mask[(b*TV + t)*FV + f];
    ASWZ_W[(AOFF_G3 + t*AG3_STRIDE + aidx16(b, FV + f, 32)) >> 1] =
        pack2h(src[0], src[1]);
}

// h init: plain h0 + swizzled fp16 h0*gammaH[0] (run after P1 GEMM)
__global__ void hAinit_k(const float* __restrict__ h0) {
    int idx = blockIdx.x * 256 + threadIdx.x;   // B*H/2 pairs
    int b = idx >> 9, j = (idx & 511) * 2;
    int e = b*HV + j;
    float ha = h0[e], hb = h0[e+1];
    g_h[e] = ha; g_h[e+1] = hb;
    ASWZ_W[(AOFF_G1 + aidx16(b, j, 64)) >> 1] =
        pack2h(ha * g_gammaH[e], hb * g_gammaH[e+1]);
}

// ---------------- epilogues ----------------

struct EP_P1 {
    const float* bdh;
    static constexpr bool RED = false;
    __device__ float operator()(int m, int n, float v) const {
        g_gammaH[(size_t)m*HV + n] = expf(-fmaxf(v + bdh[n], 0.f));
        return 0.f;
    }
    __device__ void store_partial(int, float) const {}
};
struct EP_P2 {
    const float* bwc;
    static constexpr bool RED = false;
    __device__ float operator()(int m, int n, float v) const {
        g_beta[(size_t)m*FV + n] = v + bwc[n];
        return 0.f;
    }
    __device__ void store_partial(int, float) const {}
};
struct EP_G1 {
    const float* bh; const float* bhh; const float* x; const float* mask; int t;
    static constexpr bool RED = false;
    __device__ float operator()(int m, int n, float v) const {
        if (n < FV) {
            float xh = v + bh[n];
            g_xh[m*FV + n] = xh;
            int idx = (m*TV + t)*FV + n;
            float mt = mask[idx];
            float xr = mt * x[idx] + (1.f - mt) * xh;
            ASWZ_H[AOFF_G2 + aidx16(m, n, 16)] = f2h(xr);
        } else {
            g_gh[m*3*HV + (n - FV)] = v + bhh[n - FV];
        }
        return 0.f;
    }
    __device__ void store_partial(int, float) const {}
};
struct EP_G2 {
    const float* bfr; const float* x; const float* mask;
    float* rec; float* ximp; int t;
    static constexpr bool RED = true;
    __device__ float operator()(int m, int n, float v) const {
        float xu = v + bfr[n];
        float xh = g_xh[m*FV + n];
        float be = g_beta[(size_t)t*BV*FV + m*FV + n];
        float xc = be * xu + (1.f - be) * xh;
        int idx = (m*TV + t)*FV + n;
        float mt = mask[idx], xt = x[idx];
        rec[idx]  = xc;
        float xi = mt * xt + (1.f - mt) * xc;
        ximp[idx] = xi;
        ASWZ_H[AOFF_G3 + t*AG3_STRIDE + aidx16(m, n, 32)] = f2h(xi);
        return fabsf(xc - xt) * mt;
    }
    __device__ void store_partial(int lin, float v) const {
        g_lossPart[t*NB2 + lin] = v;
    }
};
struct EP_G3 {
    const float* bih;
    static constexpr bool RED = false;
    __device__ float operator()(int m, int n, float v) const {
        g_gi[m*3*HV + n] = v + bih[n];
        return 0.f;
    }
    __device__ void store_partial(int, float) const {}
};

// ---------------- elementwise kernels ----------------

__global__ void msum_k(const float* __restrict__ mask) {
    int t = blockIdx.x;
    float s = 0.f;
    for (int i = threadIdx.x; i < BV*FV; i += 256) {
        int b = i >> 8, f = i & 255;
        s += mask[(b*TV + t)*FV + f];
    }
    __shared__ float red[256];
    red[threadIdx.x] = s;
    __syncthreads();
    for (int st = 128; st > 0; st >>= 1) {
        if (threadIdx.x < st) red[threadIdx.x] += red[threadIdx.x + st];
        __syncthreads();
    }
    if (threadIdx.x == 0) g_msum[t] = red[0];
}

// GRU update (paired j); PDL-aware
__global__ void gru_k(int t, float* __restrict__ hfin) {
    int idx = blockIdx.x * blockDim.x + threadIdx.x;  // B*H/2 pairs
    int b = idx >> 9, j = (idx & 511) * 2;
    int e = b*HV + j;
    gdc_wait();   // g_gi written by predecessor (G3)
    float hn2[2];
    #pragma unroll
    for (int u = 0; u < 2; u++) {
        float hd = g_h[e+u] * g_gammaH[(size_t)t*BV*HV + e+u];
        int base = b*3*HV + j + u;
        float r = 1.f / (1.f + expf(-(g_gi[base]        + g_gh[base])));
        float z = 1.f / (1.f + expf(-(g_gi[base + HV]   + g_gh[base + HV])));
        float n = tanhf(g_gi[base + 2*HV] + r * g_gh[base + 2*HV]);
        float hn = (1.f - z) * n + z * hd;
        g_h[e+u] = hn;
        hn2[u] = hn;
        if (hfin) hfin[e+u] = hn;
    }
    if (t + 1 < TV)
        ASWZ_W[(AOFF_G1 + aidx16(b, j, 64)) >> 1] =
            pack2h(hn2[0] * g_gammaH[(size_t)(t+1)*BV*HV + e],
                   hn2[1] * g_gammaH[(size_t)(t+1)*BV*HV + e + 1]);
    gdc_launch();
}

__global__ void final_k(float* __restrict__ out) {
    __shared__ float s[TV];
    int t = threadIdx.x;  // 64 threads
    float acc = 0.f;
    for (int i = 0; i < NB2; i++) acc += g_lossPart[t*NB2 + i];
    s[t] = acc / (g_msum[t] + 1e-12f);
    __syncthreads();
    if (t == 0) {
        float L = 0.f;
        for (int i = 0; i < TV; i++) L += s[i];
        out[OFF_LOSS]     = L;
        out[OFF_LOSS + 1] = 0.f;  // kl_loss
    }
}

// ---------------- launch ----------------

template<class KF, class... Args>
static inline void launch_pdl(KF kf, dim3 grid, dim3 block, Args... args) {
    cudaLaunchConfig_t cfg = {};
    cfg.gridDim = grid;
    cfg.blockDim = block;
    cfg.dynamicSmemBytes = 0;
    cfg.stream = 0;
    cudaLaunchAttribute at[1];
    at[0].id = cudaLaunchAttributeProgrammaticStreamSerialization;
    at[0].val.programmaticStreamSerializationAllowed = 1;
    cfg.attrs = at;
    cfg.numAttrs = 1;
    cudaLaunchKernelEx(&cfg, kf, args...);
}

extern "C" void kernel_launch(void* const* d_in, const int* in_sizes, int n_in,
                              void* d_out, int out_size) {
    const float* x      = (const float*)d_in[0];
    const float* mask   = (const float*)d_in[1];
    const float* deltas = (const float*)d_in[2];
    const float* h0     = (const float*)d_in[3];
    const float* Wdh    = (const float*)d_in[4];
    const float* bdh    = (const float*)d_in[5];
    const float* Wdx    = (const float*)d_in[6];
    const float* bdx    = (const float*)d_in[7];
    const float* Wh     = (const float*)d_in[8];
    const float* bh     = (const float*)d_in[9];
    const float* Wfr    = (const float*)d_in[10];
    const float* bfr    = (const float*)d_in[11];
    const float* Wwc    = (const float*)d_in[12];
    const float* bwc    = (const float*)d_in[13];
    const float* Wih    = (const float*)d_in[14];
    const float* bih    = (const float*)d_in[15];
    const float* Whh    = (const float*)d_in[16];
    const float* bhh    = (const float*)d_in[17];

    float* out      = (float*)d_out;
    float* ximp_out = out;
    float* rec_out  = out + OFF_REC;
    float* hfin     = out + OFF_HFIN;

    msum_k<<<TV, 256>>>(mask);

    // Pre-swizzle weights (B operands)
    swz_k<<<(3328*1024/2)/256, 256>>>(BOFF_G1, 3328, 1024, BL_G1{Wh, Whh});
    swz_k<<<(3072*512 /2)/256, 256>>>(BOFF_G3, 3072, 512,  BL_G3{Wih});
    swz_k<<<(256*256  /2)/256, 256>>>(BOFF_G2, 256,  256,  BL_G2{Wfr});
    swz_k<<<(1024*256 /2)/256, 256>>>(BOFF_P1, 1024, 256,  BL_P1{Wdh});
    swz_k<<<(256*512  /2)/256, 256>>>(BOFF_P2, 256,  512,  BL_P2{Wwc});

    // Pre-swizzle A operands for P1/P2 and G3 mask half
    swzA_P1_k<<<(32768*128)/256, 256>>>(deltas);
    swzA_P2_k<<<(32768*256)/256, 256>>>(deltas, mask, Wdx, bdx);
    swzA_G3m_k<<<(TV*BV*128)/256, 256>>>(mask);

    // P1: gammaH, M=32768, N=1024, K=256
    tgemm4_k<64,128,32,32><<<dim3(1024/128, 32768/64), 256>>>(
        FV, AOFF_P1, BOFF_P1, EP_P1{bdh});

    // h init (needs gammaH[0])
    hAinit_k<<<(BV*HV/2)/256, 256>>>(h0);

    // P2: beta, M=32768, N=256, K=512
    tgemm4_k<64,128,32,32><<<dim3(256/128, 32768/64), 256>>>(
        2*FV, AOFF_P2, BOFF_P2, EP_P2{bwc});

    for (int t = 0; t < TV; t++) {
        // G1: [x_h | gh], M=512, N=3328, K=1024 -> 208 blocks
        launch_pdl(tgemm4_k<64,128,32,32,EP_G1>, dim3(3328/128, 512/64), dim3(256),
                   HV, AOFF_G1, BOFF_G1, EP_G1{bh, bhh, x, mask, t});

        // G2: xu + combine/imputation/loss, 32 blocks
        launch_pdl(tgemm4_k<64,64,32,16,EP_G2>, dim3(256/64, 512/64), dim3(256),
                   FV, AOFF_G2, BOFF_G2, EP_G2{bfr, x, mask, rec_out, ximp_out, t});

        // G3: gi, M=512, N=3072, K=512 -> 192 blocks
        launch_pdl(tgemm4_k<64,128,32,32,EP_G3>, dim3(3072/128, 512/64), dim3(256),
                   2*FV, AOFF_G3 + t*AG3_STRIDE, BOFF_G3, EP_G3{bih});

        // GRU elementwise update (+ next step's swizzled A)
        launch_pdl(gru_k, dim3((BV*HV/2)/256), dim3(256),
                   t, (t == TV-1) ? hfin : (float*)nullptr);
    }

    final_k<<<1, TV>>>(out);
}